// round 1
// baseline (speedup 1.0000x reference)
#include <cuda_runtime.h>
#include <math.h>

// ---------------- Problem constants (fixed by reference) ----------------
#define Bz   16
#define Lz   1024
#define DMz  512
#define Hz   8
#define DKz  64
#define DVz  64
#define DHz  2048
#define Uz   35          // FACTOR * ceil(ln(1024)) = 5*7
#define BHz  (Bz*Hz)     // 128
#define ROWSz (Bz*Lz)    // 16384
#define EPSz 1e-5f

// ---------------- Scratch (device globals; no allocation) ----------------
__device__ float g_Q[ROWSz*DMz];        // (B,L,H*DK)
__device__ float g_K[ROWSz*DMz];
__device__ float g_V[ROWSz*DMz];
__device__ float g_M[BHz*Lz];
__device__ int   g_Mtop[BHz*Uz];
__device__ int   g_rowmap[BHz*Lz];      // l -> u or -1
__device__ float g_attn[(size_t)BHz*Uz*Lz];
__device__ float g_ctxrow[BHz*Uz*DVz];
__device__ float g_vmean[BHz*DVz];
__device__ float g_ctx[ROWSz*DMz];
__device__ float g_y[ROWSz*DMz];
__device__ float g_x1[ROWSz*DMz];
__device__ float g_h[ROWSz*DHz];
__device__ float g_y2[ROWSz*DMz];

// ---------------- Generic 128x128x8 SGEMM with epilogues ----------------
// C = A(MxK) @ B(KxN) + bias ; epi: 0 = bias only, 1 = bias+residual, 2 = bias+relu
// M % 128 == 0, N % 128 == 0, K % 8 == 0 (always true here)
__global__ void __launch_bounds__(256)
sgemm_kernel(const float* __restrict__ A, const float* __restrict__ Bm,
             const float* __restrict__ bias, const float* __restrict__ res,
             float* __restrict__ C, int M, int N, int K, int epi)
{
    __shared__ float As[8][128];
    __shared__ float Bs[8][128];
    const int tid = threadIdx.x;
    const int bm = blockIdx.y * 128;
    const int bn = blockIdx.x * 128;

    const int arow = tid >> 1, acol = (tid & 1) * 4;   // A tile load coords
    const int brow = tid >> 5, bcol = (tid & 31) * 4;  // B tile load coords
    const int tx = tid & 15, ty = tid >> 4;            // 16x16 thread grid, 8x8 micro

    float acc[8][8];
#pragma unroll
    for (int i = 0; i < 8; i++)
#pragma unroll
        for (int j = 0; j < 8; j++) acc[i][j] = 0.f;

    for (int k0 = 0; k0 < K; k0 += 8) {
        float4 av = *(const float4*)&A[(size_t)(bm + arow) * K + k0 + acol];
        As[acol + 0][arow] = av.x;
        As[acol + 1][arow] = av.y;
        As[acol + 2][arow] = av.z;
        As[acol + 3][arow] = av.w;
        float4 bv = *(const float4*)&Bm[(size_t)(k0 + brow) * N + bn + bcol];
        *(float4*)&Bs[brow][bcol] = bv;
        __syncthreads();
#pragma unroll
        for (int kk = 0; kk < 8; kk++) {
            float a[8], b[8];
            float4 a0 = *(const float4*)&As[kk][ty * 8];
            float4 a1 = *(const float4*)&As[kk][ty * 8 + 4];
            a[0]=a0.x; a[1]=a0.y; a[2]=a0.z; a[3]=a0.w;
            a[4]=a1.x; a[5]=a1.y; a[6]=a1.z; a[7]=a1.w;
            float4 b0 = *(const float4*)&Bs[kk][tx * 8];
            float4 b1 = *(const float4*)&Bs[kk][tx * 8 + 4];
            b[0]=b0.x; b[1]=b0.y; b[2]=b0.z; b[3]=b0.w;
            b[4]=b1.x; b[5]=b1.y; b[6]=b1.z; b[7]=b1.w;
#pragma unroll
            for (int i = 0; i < 8; i++)
#pragma unroll
                for (int j = 0; j < 8; j++) acc[i][j] += a[i] * b[j];
        }
        __syncthreads();
    }

#pragma unroll
    for (int i = 0; i < 8; i++) {
        const int row = bm + ty * 8 + i;
        float* crow = C + (size_t)row * N + bn + tx * 8;
        const float* brw = bias + bn + tx * 8;
        const float* rrw = res ? res + (size_t)row * N + bn + tx * 8 : nullptr;
#pragma unroll
        for (int j = 0; j < 8; j++) {
            float v = acc[i][j] + brw[j];
            if (epi == 1) v += rrw[j];
            else if (epi == 2) v = fmaxf(v, 0.f);
            crow[j] = v;
        }
    }
}

// ---------------- Sampled scores M = max_s(QK) - mean_s(QK) ----------------
__global__ void compute_m_kernel(const int* __restrict__ idx)
{
    const int gw = (blockIdx.x * blockDim.x + threadIdx.x) >> 5;
    const int lane = threadIdx.x & 31;
    if (gw >= BHz * Lz) return;
    const int l = gw & (Lz - 1);
    const int bh = gw >> 10;
    const int h = bh & (Hz - 1), b = bh >> 3;

    const float* qrow = g_Q + (size_t)(b * Lz + l) * DMz + h * DKz;
    const float q0 = qrow[lane], q1 = qrow[lane + 32];
    float mx = -INFINITY, sum = 0.f;
#pragma unroll 1
    for (int s = 0; s < Uz; s++) {
        const int j = idx[l * Uz + s];
        const float* krow = g_K + (size_t)(b * Lz + j) * DMz + h * DKz;
        float p = q0 * krow[lane] + q1 * krow[lane + 32];
#pragma unroll
        for (int o = 16; o; o >>= 1) p += __shfl_xor_sync(0xffffffffu, p, o);
        mx = fmaxf(mx, p);
        sum += p;
    }
    if (lane == 0) g_M[bh * Lz + l] = mx - sum * (1.0f / Uz);
}

// ---------------- top-35 per (b,h), tie -> smallest index ----------------
__global__ void __launch_bounds__(256) topk_kernel()
{
    const int bh = blockIdx.x;
    const int tid = threadIdx.x;
    __shared__ float vals[Lz];
    __shared__ float rv[256];
    __shared__ int   ri[256];

    for (int l = tid; l < Lz; l += 256) {
        vals[l] = g_M[bh * Lz + l];
        g_rowmap[bh * Lz + l] = -1;
    }
    __syncthreads();

    for (int u = 0; u < Uz; u++) {
        float best = -INFINITY; int bi = -1;
        for (int l = tid; l < Lz; l += 256) {
            float v = vals[l];
            if (v > best) { best = v; bi = l; }
        }
        rv[tid] = best; ri[tid] = bi;
        __syncthreads();
        for (int s = 128; s; s >>= 1) {
            if (tid < s) {
                float ov = rv[tid + s]; int oi = ri[tid + s];
                if (ov > rv[tid] ||
                    (ov == rv[tid] && (unsigned)oi < (unsigned)ri[tid])) {
                    rv[tid] = ov; ri[tid] = oi;
                }
            }
            __syncthreads();
        }
        if (tid == 0) {
            const int sel = ri[0];
            g_Mtop[bh * Uz + u] = sel;
            g_rowmap[bh * Lz + sel] = u;
            vals[sel] = -INFINITY;
        }
        __syncthreads();
    }
}

// ---------------- scores = Q_top @ K^T / 8 ----------------
__global__ void __launch_bounds__(256) scores_kernel()
{
    const int bh = blockIdx.x;
    const int b = bh >> 3, h = bh & (Hz - 1);
    const int tid = threadIdx.x;
    __shared__ float Qr[Uz * DKz];

    for (int i = tid; i < Uz * DKz; i += 256) {
        const int u = i / DKz, d = i - u * DKz;
        const int l = g_Mtop[bh * Uz + u];
        Qr[i] = g_Q[(size_t)(b * Lz + l) * DMz + h * DKz + d];
    }
    __syncthreads();

    for (int l = tid; l < Lz; l += 256) {
        float acc[Uz];
#pragma unroll
        for (int u = 0; u < Uz; u++) acc[u] = 0.f;
        const float* krow = g_K + (size_t)(b * Lz + l) * DMz + h * DKz;
#pragma unroll 4
        for (int d = 0; d < DKz; d++) {
            const float kd = krow[d];
#pragma unroll
            for (int u = 0; u < Uz; u++) acc[u] += kd * Qr[u * DKz + d];
        }
#pragma unroll
        for (int u = 0; u < Uz; u++)
            g_attn[((size_t)bh * Uz + u) * Lz + l] = acc[u] * 0.125f;
    }
}

// ---------------- row softmax over L ----------------
__global__ void __launch_bounds__(256) softmax_kernel()
{
    const int row = blockIdx.x;          // bh*U + u
    float* p = g_attn + (size_t)row * Lz;
    const int tid = threadIdx.x;
    __shared__ float red[256];

    float4 v = ((float4*)p)[tid];
    float m = fmaxf(fmaxf(v.x, v.y), fmaxf(v.z, v.w));
    red[tid] = m; __syncthreads();
    for (int s = 128; s; s >>= 1) { if (tid < s) red[tid] = fmaxf(red[tid], red[tid + s]); __syncthreads(); }
    m = red[0]; __syncthreads();

    v.x = __expf(v.x - m); v.y = __expf(v.y - m);
    v.z = __expf(v.z - m); v.w = __expf(v.w - m);
    red[tid] = v.x + v.y + v.z + v.w; __syncthreads();
    for (int s = 128; s; s >>= 1) { if (tid < s) red[tid] += red[tid + s]; __syncthreads(); }
    const float inv = 1.0f / red[0];
    v.x *= inv; v.y *= inv; v.z *= inv; v.w *= inv;
    ((float4*)p)[tid] = v;
}

// ---------------- context rows = attn @ V ----------------
__global__ void context_kernel()
{
    const int bhu = blockIdx.x;          // bh*U + u
    const int bh = bhu / Uz;
    const int b = bh >> 3, h = bh & (Hz - 1);
    const int d = threadIdx.x;           // 64
    const float* a = g_attn + (size_t)bhu * Lz;
    float acc = 0.f;
    const float* vbase = g_V + (size_t)(b * Lz) * DMz + h * DVz + d;
#pragma unroll 4
    for (int l = 0; l < Lz; l++) acc += a[l] * vbase[(size_t)l * DMz];
    g_ctxrow[bhu * DVz + d] = acc;
}

// ---------------- V mean over L ----------------
__global__ void vmean_kernel()
{
    const int bh = blockIdx.x;
    const int b = bh >> 3, h = bh & (Hz - 1);
    const int d = threadIdx.x;           // 64
    float acc = 0.f;
    const float* vbase = g_V + (size_t)(b * Lz) * DMz + h * DVz + d;
#pragma unroll 4
    for (int l = 0; l < Lz; l++) acc += vbase[(size_t)l * DMz];
    g_vmean[bh * DVz + d] = acc * (1.0f / Lz);
}

// ---------------- score output: fill 1/L or copy attn row ----------------
__global__ void __launch_bounds__(256) write_scores_kernel(float* __restrict__ outp)
{
    const int row = blockIdx.x;          // bh*L + l  (== (b,h,l) linearized)
    const int bh = row >> 10;
    const int u = g_rowmap[row];
    float4* dst = (float4*)(outp + (size_t)row * Lz);
    const int tid = threadIdx.x;
    if (u < 0) {
        const float c = 1.0f / Lz;
        dst[tid] = make_float4(c, c, c, c);
    } else {
        const float4* src = (const float4*)(g_attn + ((size_t)bh * Uz + u) * Lz);
        dst[tid] = src[tid];
    }
}

// ---------------- assemble ctx (B,L,H*DV) ----------------
__global__ void __launch_bounds__(256) ctx_assemble_kernel()
{
    const size_t gidx = (size_t)blockIdx.x * 256 + threadIdx.x;  // over ROWS*DM
    const int row = (int)(gidx >> 9);        // b*L + l
    const int c = (int)(gidx & 511);         // h*64 + d
    const int h = c >> 6, d = c & 63;
    const int b = row >> 10, l = row & (Lz - 1);
    const int bh = b * Hz + h;
    const int u = g_rowmap[bh * Lz + l];
    float v = (u < 0) ? g_vmean[bh * DVz + d]
                      : g_ctxrow[(bh * Uz + u) * DVz + d];
    g_ctx[gidx] = v;
}

// ---------------- LayerNorm over last dim (512) ----------------
__global__ void __launch_bounds__(256)
ln_kernel(const float* __restrict__ in, const float* __restrict__ g,
          const float* __restrict__ beta, float* __restrict__ out)
{
    const int row = blockIdx.x;
    const int tid = threadIdx.x;
    __shared__ float red[256];
    const float* r = in + (size_t)row * DMz;
    const float a = r[tid], b2 = r[tid + 256];

    red[tid] = a + b2; __syncthreads();
    for (int s = 128; s; s >>= 1) { if (tid < s) red[tid] += red[tid + s]; __syncthreads(); }
    const float mean = red[0] * (1.0f / DMz);
    __syncthreads();
    const float d0 = a - mean, d1 = b2 - mean;
    red[tid] = d0 * d0 + d1 * d1; __syncthreads();
    for (int s = 128; s; s >>= 1) { if (tid < s) red[tid] += red[tid + s]; __syncthreads(); }
    const float inv = rsqrtf(red[0] * (1.0f / DMz) + EPSz);
    out[(size_t)row * DMz + tid]       = g[tid]       * d0 * inv + beta[tid];
    out[(size_t)row * DMz + tid + 256] = g[tid + 256] * d1 * inv + beta[tid + 256];
}

// ---------------- launch ----------------
extern "C" void kernel_launch(void* const* d_in, const int* in_sizes, int n_in,
                              void* d_out, int out_size)
{
    const float* x   = (const float*)d_in[0];
    const float* Wq  = (const float*)d_in[1];
    const float* bq  = (const float*)d_in[2];
    const float* Wk  = (const float*)d_in[3];
    const float* bk  = (const float*)d_in[4];
    const float* Wv  = (const float*)d_in[5];
    const float* bv  = (const float*)d_in[6];
    const float* Wo  = (const float*)d_in[7];
    const float* bo  = (const float*)d_in[8];
    const float* g1  = (const float*)d_in[9];
    const float* be1 = (const float*)d_in[10];
    const float* W1  = (const float*)d_in[11];
    const float* bf1 = (const float*)d_in[12];
    const float* W2  = (const float*)d_in[13];
    const float* bf2 = (const float*)d_in[14];
    const float* g2  = (const float*)d_in[15];
    const float* be2 = (const float*)d_in[16];
    const int*   idx = (const int*)d_in[17];
    float* out = (float*)d_out;

    float *Qp, *Kp, *Vp, *ctxp, *yp, *x1p, *hp, *y2p;
    cudaGetSymbolAddress((void**)&Qp,  g_Q);
    cudaGetSymbolAddress((void**)&Kp,  g_K);
    cudaGetSymbolAddress((void**)&Vp,  g_V);
    cudaGetSymbolAddress((void**)&ctxp, g_ctx);
    cudaGetSymbolAddress((void**)&yp,  g_y);
    cudaGetSymbolAddress((void**)&x1p, g_x1);
    cudaGetSymbolAddress((void**)&hp,  g_h);
    cudaGetSymbolAddress((void**)&y2p, g_y2);

    const dim3 g512(DMz / 128, ROWSz / 128);   // (4, 128)
    const dim3 g2048(DHz / 128, ROWSz / 128);  // (16, 128)

    // 1) Q, K, V projections
    sgemm_kernel<<<g512, 256>>>(x, Wq, bq, nullptr, Qp, ROWSz, DMz, DMz, 0);
    sgemm_kernel<<<g512, 256>>>(x, Wk, bk, nullptr, Kp, ROWSz, DMz, DMz, 0);
    sgemm_kernel<<<g512, 256>>>(x, Wv, bv, nullptr, Vp, ROWSz, DMz, DMz, 0);

    // 2) sampled measurement M, top-k, scores, softmax
    compute_m_kernel<<<(BHz * Lz) / 8, 256>>>(idx);
    topk_kernel<<<BHz, 256>>>();
    scores_kernel<<<BHz, 256>>>();
    softmax_kernel<<<BHz * Uz, 256>>>();

    // 3) context rows, V mean
    context_kernel<<<BHz * Uz, DVz>>>();
    vmean_kernel<<<BHz, DVz>>>();

    // 4) score output (second element of the tuple), if present
    if (out_size >= (int)(ROWSz * DMz) + BHz * Lz * (Lz / 1) / 1 &&
        (size_t)out_size >= (size_t)ROWSz * DMz + (size_t)BHz * Lz * Lz) {
        write_scores_kernel<<<BHz * Lz, 256>>>(out + (size_t)ROWSz * DMz);
    }

    // 5) assemble ctx, output projection + residual, LN1
    ctx_assemble_kernel<<<(ROWSz * DMz) / 256, 256>>>();
    sgemm_kernel<<<g512, 256>>>(ctxp, Wo, bo, x, yp, ROWSz, DMz, DMz, 1);
    ln_kernel<<<ROWSz, 256>>>(yp, g1, be1, x1p);

    // 6) FFN + residual, LN2 -> x2 into d_out
    sgemm_kernel<<<g2048, 256>>>(x1p, W1, bf1, nullptr, hp, ROWSz, DHz, DMz, 2);
    sgemm_kernel<<<g512, 256>>>(hp, W2, bf2, x1p, y2p, ROWSz, DMz, DHz, 1);
    ln_kernel<<<ROWSz, 256>>>(y2p, g2, be2, out);
}

// round 4
// speedup vs baseline: 1.7112x; 1.7112x over previous
#include <cuda_runtime.h>
#include <cuda_bf16.h>
#include <math.h>
#include <stdint.h>

// ---------------- Problem constants ----------------
#define Bz   16
#define Lz   1024
#define DMz  512
#define Hz   8
#define DKz  64
#define DVz  64
#define DHz  2048
#define Uz   35
#define BHz  (Bz*Hz)     // 128
#define ROWSz (Bz*Lz)    // 16384
#define EPSz 1e-5f

// ---------------- fp32 scratch ----------------
__device__ float g_Q[ROWSz*DMz];
__device__ float g_K[ROWSz*DMz];
__device__ float g_V[ROWSz*DMz];
__device__ float g_M[BHz*Lz];
__device__ int   g_Mtop[BHz*Uz];
__device__ int   g_rowmap[BHz*Lz];
__device__ float g_attn[(size_t)BHz*Uz*Lz];
__device__ float g_ctxrow[BHz*Uz*DVz];
__device__ float g_vmean[BHz*DVz];
__device__ float g_ctx[ROWSz*DMz];
__device__ float g_y[ROWSz*DMz];
__device__ float g_x1[ROWSz*DMz];
__device__ float g_h[(size_t)ROWSz*DHz];
__device__ float g_y2[ROWSz*DMz];

// ---------------- bf16 split scratch ----------------
__device__ __nv_bfloat16 g_xh[ROWSz*DMz], g_xl[ROWSz*DMz];
__device__ __nv_bfloat16 g_ah[(size_t)ROWSz*DHz], g_al[(size_t)ROWSz*DHz];
__device__ __nv_bfloat16 g_WqTh[DMz*DMz], g_WqTl[DMz*DMz];
__device__ __nv_bfloat16 g_WkTh[DMz*DMz], g_WkTl[DMz*DMz];
__device__ __nv_bfloat16 g_WvTh[DMz*DMz], g_WvTl[DMz*DMz];
__device__ __nv_bfloat16 g_WoTh[DMz*DMz], g_WoTl[DMz*DMz];
__device__ __nv_bfloat16 g_W1Th[DMz*DHz], g_W1Tl[DMz*DHz];
__device__ __nv_bfloat16 g_W2Th[DHz*DMz], g_W2Tl[DHz*DMz];

// ---------------- helpers ----------------
__device__ __forceinline__ void cp16(uint32_t s, const void* g) {
    asm volatile("cp.async.cg.shared.global [%0], [%1], 16;"
                 :: "r"(s), "l"(__cvta_generic_to_global(g)));
}
__device__ __forceinline__ void cp_commit() {
    asm volatile("cp.async.commit_group;" ::: "memory");
}
__device__ __forceinline__ void ldm_x4(uint32_t& r0, uint32_t& r1, uint32_t& r2, uint32_t& r3,
                                       uint32_t addr) {
    asm volatile("ldmatrix.sync.aligned.m8n8.x4.shared.b16 {%0,%1,%2,%3}, [%4];"
                 : "=r"(r0), "=r"(r1), "=r"(r2), "=r"(r3) : "r"(addr));
}
__device__ __forceinline__ void mma16816(float* c, const uint32_t* a, const uint32_t* b) {
    asm volatile("mma.sync.aligned.m16n8k16.row.col.f32.bf16.bf16.f32 "
                 "{%0,%1,%2,%3}, {%4,%5,%6,%7}, {%8,%9}, {%0,%1,%2,%3};"
                 : "+f"(c[0]), "+f"(c[1]), "+f"(c[2]), "+f"(c[3])
                 : "r"(a[0]), "r"(a[1]), "r"(a[2]), "r"(a[3]), "r"(b[0]), "r"(b[1]));
}

// ---------------- mma.sync bf16-split GEMM ----------------
// C(MxN) = Ahi@Bhi + Ahi@Blo + Alo@Bhi (+bias) [+res | relu]
// A row-major [M][K] bf16; B K-major transposed [N][K] bf16.
// Tile BM=BN=128, BK=32, 256 threads (8 warps of 64x32).
// SMEM rows padded to 80B (32 bf16 + 8 pad) -> conflict-free ldmatrix.
#define ROWB 80
#define STAGE (128 * ROWB)          // 10240 B per operand tile

__global__ void __launch_bounds__(256, 2)
gemm_bf16_kernel(const __nv_bfloat16* __restrict__ Ahi, const __nv_bfloat16* __restrict__ Alo,
                 const __nv_bfloat16* __restrict__ Bhi, const __nv_bfloat16* __restrict__ Blo,
                 const float* __restrict__ bias, const float* __restrict__ res,
                 float* __restrict__ C, int M, int N, int K, int eop)
{
    __shared__ __align__(16) char smem[2 * 2 * STAGE];  // [buf][A|B]
    const uint32_t smem_u = (uint32_t)__cvta_generic_to_shared(smem);

    const int tid = threadIdx.x;
    const int wid = tid >> 5, lane = tid & 31;
    const int wm = (wid >> 2) * 64;      // warp m offset in tile
    const int wn = (wid & 3) * 32;       // warp n offset in tile
    const int g = lane >> 3, r = lane & 7;
    const int bm = blockIdx.y * 128;
    const int bn = blockIdx.x * 128;

    const int kt = K >> 5;               // 32-wide k tiles per pass
    const int T = 3 * kt;

    float acc[4][4][4];
#pragma unroll
    for (int i = 0; i < 4; i++)
#pragma unroll
        for (int j = 0; j < 4; j++)
#pragma unroll
            for (int c = 0; c < 4; c++) acc[i][j][c] = 0.f;

    // chunk coords for loads: 512 16B-chunks per operand tile, 2 per thread
    const int ch0 = tid, ch1 = tid + 256;
    const int ar0 = ch0 >> 2, ac0 = ch0 & 3;
    const int ar1 = ch1 >> 2, ac1 = ch1 & 3;

    auto load_tile = [&](int it, int buf) {
        const int p = it / kt;
        const int kk = (it - p * kt) << 5;
        const __nv_bfloat16* Ap = (p < 2) ? Ahi : Alo;
        const __nv_bfloat16* Bp = (p == 1) ? Blo : Bhi;
        const uint32_t sA = smem_u + buf * 2 * STAGE;
        const uint32_t sB = sA + STAGE;
        cp16(sA + ar0 * ROWB + ac0 * 16, Ap + (size_t)(bm + ar0) * K + kk + ac0 * 8);
        cp16(sA + ar1 * ROWB + ac1 * 16, Ap + (size_t)(bm + ar1) * K + kk + ac1 * 8);
        cp16(sB + ar0 * ROWB + ac0 * 16, Bp + (size_t)(bn + ar0) * K + kk + ac0 * 8);
        cp16(sB + ar1 * ROWB + ac1 * 16, Bp + (size_t)(bn + ar1) * K + kk + ac1 * 8);
        cp_commit();
    };

    load_tile(0, 0);

    for (int it = 0; it < T; it++) {
        const int buf = it & 1;
        if (it + 1 < T) {
            load_tile(it + 1, buf ^ 1);
            asm volatile("cp.async.wait_group 1;" ::: "memory");
        } else {
            asm volatile("cp.async.wait_group 0;" ::: "memory");
        }
        __syncthreads();

        const uint32_t sA = smem_u + buf * 2 * STAGE;
        const uint32_t sB = sA + STAGE;
#pragma unroll
        for (int s = 0; s < 2; s++) {
            uint32_t af[4][4];
#pragma unroll
            for (int mf = 0; mf < 4; mf++) {
                const int row = wm + mf * 16 + ((g & 1) << 3) + r;
                const int chk = 2 * s + (g >> 1);
                ldm_x4(af[mf][0], af[mf][1], af[mf][2], af[mf][3],
                       sA + row * ROWB + chk * 16);
            }
            uint32_t bf[4][2];
#pragma unroll
            for (int ng = 0; ng < 2; ng++) {
                const int row = wn + ng * 16 + ((g >> 1) << 3) + r;
                const int chk = 2 * s + (g & 1);
                ldm_x4(bf[2 * ng][0], bf[2 * ng][1], bf[2 * ng + 1][0], bf[2 * ng + 1][1],
                       sB + row * ROWB + chk * 16);
            }
#pragma unroll
            for (int mf = 0; mf < 4; mf++)
#pragma unroll
                for (int nf = 0; nf < 4; nf++)
                    mma16816(acc[mf][nf], af[mf], bf[nf]);
        }
        __syncthreads();
    }

    // epilogue
    const int rl = lane >> 2, cl = (lane & 3) * 2;
#pragma unroll
    for (int mf = 0; mf < 4; mf++) {
        const int row0 = bm + wm + mf * 16 + rl;
#pragma unroll
        for (int nf = 0; nf < 4; nf++) {
            const int col = bn + wn + nf * 8 + cl;
            const float b0 = bias[col], b1 = bias[col + 1];
            float v0 = acc[mf][nf][0] + b0, v1 = acc[mf][nf][1] + b1;
            float v2 = acc[mf][nf][2] + b0, v3 = acc[mf][nf][3] + b1;
            if (eop == 1) {
                const float* r0 = res + (size_t)row0 * N + col;
                const float* r1 = res + (size_t)(row0 + 8) * N + col;
                v0 += r0[0]; v1 += r0[1]; v2 += r1[0]; v3 += r1[1];
            } else if (eop == 2) {
                v0 = fmaxf(v0, 0.f); v1 = fmaxf(v1, 0.f);
                v2 = fmaxf(v2, 0.f); v3 = fmaxf(v3, 0.f);
            }
            *(float2*)(C + (size_t)row0 * N + col) = make_float2(v0, v1);
            *(float2*)(C + (size_t)(row0 + 8) * N + col) = make_float2(v2, v3);
        }
    }
}

// ---------------- fp32 -> bf16 hi/lo split ----------------
__global__ void __launch_bounds__(256)
split_kernel(const float* __restrict__ src, __nv_bfloat16* __restrict__ hi,
             __nv_bfloat16* __restrict__ lo)
{
    const size_t i = (size_t)blockIdx.x * 256 + threadIdx.x;  // float4 index
    const float4 v = ((const float4*)src)[i];
    __nv_bfloat16 h0 = __float2bfloat16(v.x), h1 = __float2bfloat16(v.y);
    __nv_bfloat16 h2 = __float2bfloat16(v.z), h3 = __float2bfloat16(v.w);
    __nv_bfloat162 ha; ha.x = h0; ha.y = h1;
    __nv_bfloat162 hb; hb.x = h2; hb.y = h3;
    ((__nv_bfloat162*)hi)[i * 2 + 0] = ha;
    ((__nv_bfloat162*)hi)[i * 2 + 1] = hb;
    __nv_bfloat162 la, lb;
    la.x = __float2bfloat16(v.x - __bfloat162float(h0));
    la.y = __float2bfloat16(v.y - __bfloat162float(h1));
    lb.x = __float2bfloat16(v.z - __bfloat162float(h2));
    lb.y = __float2bfloat16(v.w - __bfloat162float(h3));
    ((__nv_bfloat162*)lo)[i * 2 + 0] = la;
    ((__nv_bfloat162*)lo)[i * 2 + 1] = lb;
}

// ---------------- weight transpose + split: W[K][N] -> WT[N][K] hi/lo ----------------
__global__ void __launch_bounds__(256)
tsplit_kernel(const float* __restrict__ src, __nv_bfloat16* __restrict__ hi,
              __nv_bfloat16* __restrict__ lo, int K, int N)
{
    __shared__ float tile[32][33];
    const int tx = threadIdx.x & 31, ty = threadIdx.x >> 5;
    const int n0 = blockIdx.x * 32, k0 = blockIdx.y * 32;
#pragma unroll
    for (int i = 0; i < 4; i++)
        tile[ty + 8 * i][tx] = src[(size_t)(k0 + ty + 8 * i) * N + n0 + tx];
    __syncthreads();
#pragma unroll
    for (int i = 0; i < 4; i++) {
        const int n = n0 + ty + 8 * i, k = k0 + tx;
        const float v = tile[tx][ty + 8 * i];
        const __nv_bfloat16 h = __float2bfloat16(v);
        hi[(size_t)n * K + k] = h;
        lo[(size_t)n * K + k] = __float2bfloat16(v - __bfloat162float(h));
    }
}

// ---------------- Sampled scores M = max_s(QK) - mean_s(QK) ----------------
__global__ void compute_m_kernel(const int* __restrict__ idx)
{
    const int gw = (blockIdx.x * blockDim.x + threadIdx.x) >> 5;
    const int lane = threadIdx.x & 31;
    if (gw >= BHz * Lz) return;
    const int l = gw & (Lz - 1);
    const int bh = gw >> 10;
    const int h = bh & (Hz - 1), b = bh >> 3;

    const float* qrow = g_Q + (size_t)(b * Lz + l) * DMz + h * DKz;
    const float q0 = qrow[lane], q1 = qrow[lane + 32];
    float mx = -INFINITY, sum = 0.f;
#pragma unroll 1
    for (int s = 0; s < Uz; s++) {
        const int j = idx[l * Uz + s];
        const float* krow = g_K + (size_t)(b * Lz + j) * DMz + h * DKz;
        float p = q0 * krow[lane] + q1 * krow[lane + 32];
#pragma unroll
        for (int o = 16; o; o >>= 1) p += __shfl_xor_sync(0xffffffffu, p, o);
        mx = fmaxf(mx, p);
        sum += p;
    }
    if (lane == 0) g_M[bh * Lz + l] = mx - sum * (1.0f / Uz);
}

// ---------------- top-35 per (b,h), tie -> smallest index ----------------
__global__ void __launch_bounds__(256) topk_kernel()
{
    const int bh = blockIdx.x;
    const int tid = threadIdx.x;
    __shared__ float vals[Lz];
    __shared__ float rv[256];
    __shared__ int   ri[256];

    for (int l = tid; l < Lz; l += 256) {
        vals[l] = g_M[bh * Lz + l];
        g_rowmap[bh * Lz + l] = -1;
    }
    __syncthreads();

    for (int u = 0; u < Uz; u++) {
        float best = -INFINITY; int bi = -1;
        for (int l = tid; l < Lz; l += 256) {
            float v = vals[l];
            if (v > best) { best = v; bi = l; }
        }
        rv[tid] = best; ri[tid] = bi;
        __syncthreads();
        for (int s = 128; s; s >>= 1) {
            if (tid < s) {
                float ov = rv[tid + s]; int oi = ri[tid + s];
                if (ov > rv[tid] ||
                    (ov == rv[tid] && (unsigned)oi < (unsigned)ri[tid])) {
                    rv[tid] = ov; ri[tid] = oi;
                }
            }
            __syncthreads();
        }
        if (tid == 0) {
            const int sel = ri[0];
            g_Mtop[bh * Uz + u] = sel;
            g_rowmap[bh * Lz + sel] = u;
            vals[sel] = -INFINITY;
        }
        __syncthreads();
    }
}

// ---------------- scores = Q_top @ K^T / 8 ----------------
__global__ void __launch_bounds__(256) scores_kernel()
{
    const int bh = blockIdx.x;
    const int b = bh >> 3, h = bh & (Hz - 1);
    const int tid = threadIdx.x;
    __shared__ float Qr[Uz * DKz];

    for (int i = tid; i < Uz * DKz; i += 256) {
        const int u = i / DKz, d = i - u * DKz;
        const int l = g_Mtop[bh * Uz + u];
        Qr[i] = g_Q[(size_t)(b * Lz + l) * DMz + h * DKz + d];
    }
    __syncthreads();

    for (int l = tid; l < Lz; l += 256) {
        float acc[Uz];
#pragma unroll
        for (int u = 0; u < Uz; u++) acc[u] = 0.f;
        const float* krow = g_K + (size_t)(b * Lz + l) * DMz + h * DKz;
#pragma unroll 4
        for (int d = 0; d < DKz; d++) {
            const float kd = krow[d];
#pragma unroll
            for (int u = 0; u < Uz; u++) acc[u] += kd * Qr[u * DKz + d];
        }
#pragma unroll
        for (int u = 0; u < Uz; u++)
            g_attn[((size_t)bh * Uz + u) * Lz + l] = acc[u] * 0.125f;
    }
}

// ---------------- row softmax over L ----------------
__global__ void __launch_bounds__(256) softmax_kernel()
{
    const int row = blockIdx.x;
    float* p = g_attn + (size_t)row * Lz;
    const int tid = threadIdx.x;
    __shared__ float red[256];

    float4 v = ((float4*)p)[tid];
    float m = fmaxf(fmaxf(v.x, v.y), fmaxf(v.z, v.w));
    red[tid] = m; __syncthreads();
    for (int s = 128; s; s >>= 1) { if (tid < s) red[tid] = fmaxf(red[tid], red[tid + s]); __syncthreads(); }
    m = red[0]; __syncthreads();

    v.x = __expf(v.x - m); v.y = __expf(v.y - m);
    v.z = __expf(v.z - m); v.w = __expf(v.w - m);
    red[tid] = v.x + v.y + v.z + v.w; __syncthreads();
    for (int s = 128; s; s >>= 1) { if (tid < s) red[tid] += red[tid + s]; __syncthreads(); }
    const float inv = 1.0f / red[0];
    v.x *= inv; v.y *= inv; v.z *= inv; v.w *= inv;
    ((float4*)p)[tid] = v;
}

// ---------------- context rows = attn @ V ----------------
__global__ void context_kernel()
{
    const int bhu = blockIdx.x;
    const int bh = bhu / Uz;
    const int b = bh >> 3, h = bh & (Hz - 1);
    const int d = threadIdx.x;
    const float* a = g_attn + (size_t)bhu * Lz;
    float acc = 0.f;
    const float* vbase = g_V + (size_t)(b * Lz) * DMz + h * DVz + d;
#pragma unroll 4
    for (int l = 0; l < Lz; l++) acc += a[l] * vbase[(size_t)l * DMz];
    g_ctxrow[bhu * DVz + d] = acc;
}

// ---------------- V mean over L ----------------
__global__ void vmean_kernel()
{
    const int bh = blockIdx.x;
    const int b = bh >> 3, h = bh & (Hz - 1);
    const int d = threadIdx.x;
    float acc = 0.f;
    const float* vbase = g_V + (size_t)(b * Lz) * DMz + h * DVz + d;
#pragma unroll 4
    for (int l = 0; l < Lz; l++) acc += vbase[(size_t)l * DMz];
    g_vmean[bh * DVz + d] = acc * (1.0f / Lz);
}

// ---------------- score output ----------------
__global__ void __launch_bounds__(256) write_scores_kernel(float* __restrict__ outp)
{
    const int row = blockIdx.x;
    const int bh = row >> 10;
    const int u = g_rowmap[row];
    float4* dst = (float4*)(outp + (size_t)row * Lz);
    const int tid = threadIdx.x;
    if (u < 0) {
        const float c = 1.0f / Lz;
        dst[tid] = make_float4(c, c, c, c);
    } else {
        const float4* src = (const float4*)(g_attn + ((size_t)bh * Uz + u) * Lz);
        dst[tid] = src[tid];
    }
}

// ---------------- assemble ctx ----------------
__global__ void __launch_bounds__(256) ctx_assemble_kernel()
{
    const size_t gidx = (size_t)blockIdx.x * 256 + threadIdx.x;
    const int row = (int)(gidx >> 9);
    const int c = (int)(gidx & 511);
    const int h = c >> 6, d = c & 63;
    const int b = row >> 10, l = row & (Lz - 1);
    const int bh = b * Hz + h;
    const int u = g_rowmap[bh * Lz + l];
    float v = (u < 0) ? g_vmean[bh * DVz + d]
                      : g_ctxrow[(bh * Uz + u) * DVz + d];
    g_ctx[gidx] = v;
}

// ---------------- LayerNorm (512) ----------------
__global__ void __launch_bounds__(256)
ln_kernel(const float* __restrict__ in, const float* __restrict__ g,
          const float* __restrict__ beta, float* __restrict__ out)
{
    const int row = blockIdx.x;
    const int tid = threadIdx.x;
    __shared__ float red[256];
    const float* r = in + (size_t)row * DMz;
    const float a = r[tid], b2 = r[tid + 256];

    red[tid] = a + b2; __syncthreads();
    for (int s = 128; s; s >>= 1) { if (tid < s) red[tid] += red[tid + s]; __syncthreads(); }
    const float mean = red[0] * (1.0f / DMz);
    __syncthreads();
    const float d0 = a - mean, d1 = b2 - mean;
    red[tid] = d0 * d0 + d1 * d1; __syncthreads();
    for (int s = 128; s; s >>= 1) { if (tid < s) red[tid] += red[tid + s]; __syncthreads(); }
    const float inv = rsqrtf(red[0] * (1.0f / DMz) + EPSz);
    out[(size_t)row * DMz + tid]       = g[tid]       * d0 * inv + beta[tid];
    out[(size_t)row * DMz + tid + 256] = g[tid + 256] * d1 * inv + beta[tid + 256];
}

// ---------------- launch ----------------
extern "C" void kernel_launch(void* const* d_in, const int* in_sizes, int n_in,
                              void* d_out, int out_size)
{
    const float* x   = (const float*)d_in[0];
    const float* Wq  = (const float*)d_in[1];
    const float* bq  = (const float*)d_in[2];
    const float* Wk  = (const float*)d_in[3];
    const float* bk  = (const float*)d_in[4];
    const float* Wv  = (const float*)d_in[5];
    const float* bv  = (const float*)d_in[6];
    const float* Wo  = (const float*)d_in[7];
    const float* bo  = (const float*)d_in[8];
    const float* g1  = (const float*)d_in[9];
    const float* be1 = (const float*)d_in[10];
    const float* W1  = (const float*)d_in[11];
    const float* bf1 = (const float*)d_in[12];
    const float* W2  = (const float*)d_in[13];
    const float* bf2 = (const float*)d_in[14];
    const float* g2  = (const float*)d_in[15];
    const float* be2 = (const float*)d_in[16];
    const int*   idx = (const int*)d_in[17];
    float* out = (float*)d_out;

    float *Qp, *Kp, *Vp, *ctxp, *yp, *x1p, *hp, *y2p;
    cudaGetSymbolAddress((void**)&Qp,   g_Q);
    cudaGetSymbolAddress((void**)&Kp,   g_K);
    cudaGetSymbolAddress((void**)&Vp,   g_V);
    cudaGetSymbolAddress((void**)&ctxp, g_ctx);
    cudaGetSymbolAddress((void**)&yp,   g_y);
    cudaGetSymbolAddress((void**)&x1p,  g_x1);
    cudaGetSymbolAddress((void**)&hp,   g_h);
    cudaGetSymbolAddress((void**)&y2p,  g_y2);

    __nv_bfloat16 *xh, *xl, *ah, *al;
    __nv_bfloat16 *WqTh, *WqTl, *WkTh, *WkTl, *WvTh, *WvTl, *WoTh, *WoTl;
    __nv_bfloat16 *W1Th, *W1Tl, *W2Th, *W2Tl;
    cudaGetSymbolAddress((void**)&xh, g_xh);   cudaGetSymbolAddress((void**)&xl, g_xl);
    cudaGetSymbolAddress((void**)&ah, g_ah);   cudaGetSymbolAddress((void**)&al, g_al);
    cudaGetSymbolAddress((void**)&WqTh, g_WqTh); cudaGetSymbolAddress((void**)&WqTl, g_WqTl);
    cudaGetSymbolAddress((void**)&WkTh, g_WkTh); cudaGetSymbolAddress((void**)&WkTl, g_WkTl);
    cudaGetSymbolAddress((void**)&WvTh, g_WvTh); cudaGetSymbolAddress((void**)&WvTl, g_WvTl);
    cudaGetSymbolAddress((void**)&WoTh, g_WoTh); cudaGetSymbolAddress((void**)&WoTl, g_WoTl);
    cudaGetSymbolAddress((void**)&W1Th, g_W1Th); cudaGetSymbolAddress((void**)&W1Tl, g_W1Tl);
    cudaGetSymbolAddress((void**)&W2Th, g_W2Th); cudaGetSymbolAddress((void**)&W2Tl, g_W2Tl);

    const dim3 gN512(4, 128);    // N=512 gemms: 128x128 tiles
    const dim3 gN2048(16, 128);  // N=2048 gemm

    // 0) conversions
    split_kernel<<<(ROWSz * DMz) / 1024, 256>>>(x, xh, xl);
    tsplit_kernel<<<dim3(16, 16), 256>>>(Wq, WqTh, WqTl, DMz, DMz);
    tsplit_kernel<<<dim3(16, 16), 256>>>(Wk, WkTh, WkTl, DMz, DMz);
    tsplit_kernel<<<dim3(16, 16), 256>>>(Wv, WvTh, WvTl, DMz, DMz);
    tsplit_kernel<<<dim3(16, 16), 256>>>(Wo, WoTh, WoTl, DMz, DMz);
    tsplit_kernel<<<dim3(64, 16), 256>>>(W1, W1Th, W1Tl, DMz, DHz);
    tsplit_kernel<<<dim3(16, 64), 256>>>(W2, W2Th, W2Tl, DHz, DMz);

    // 1) Q, K, V projections
    gemm_bf16_kernel<<<gN512, 256>>>(xh, xl, WqTh, WqTl, bq, nullptr, Qp, ROWSz, DMz, DMz, 0);
    gemm_bf16_kernel<<<gN512, 256>>>(xh, xl, WkTh, WkTl, bk, nullptr, Kp, ROWSz, DMz, DMz, 0);
    gemm_bf16_kernel<<<gN512, 256>>>(xh, xl, WvTh, WvTl, bv, nullptr, Vp, ROWSz, DMz, DMz, 0);

    // 2) ProbSparse attention
    compute_m_kernel<<<(BHz * Lz) / 8, 256>>>(idx);
    topk_kernel<<<BHz, 256>>>();
    scores_kernel<<<BHz, 256>>>();
    softmax_kernel<<<BHz * Uz, 256>>>();
    context_kernel<<<BHz * Uz, DVz>>>();
    vmean_kernel<<<BHz, DVz>>>();
    write_scores_kernel<<<BHz * Lz, 256>>>(out + (size_t)ROWSz * DMz);
    ctx_assemble_kernel<<<(ROWSz * DMz) / 256, 256>>>();

    // 3) Wo projection + residual, LN1
    split_kernel<<<(ROWSz * DMz) / 1024, 256>>>(ctxp, ah, al);
    gemm_bf16_kernel<<<gN512, 256>>>(ah, al, WoTh, WoTl, bo, x, yp, ROWSz, DMz, DMz, 1);
    ln_kernel<<<ROWSz, 256>>>(yp, g1, be1, x1p);

    // 4) FFN
    split_kernel<<<(ROWSz * DMz) / 1024, 256>>>(x1p, ah, al);
    gemm_bf16_kernel<<<gN2048, 256>>>(ah, al, W1Th, W1Tl, bf1, nullptr, hp, ROWSz, DHz, DMz, 2);
    split_kernel<<<(int)(((size_t)ROWSz * DHz) / 1024), 256>>>(hp, ah, al);
    gemm_bf16_kernel<<<gN512, 256>>>(ah, al, W2Th, W2Tl, bf2, x1p, y2p, ROWSz, DMz, DHz, 1);
    ln_kernel<<<ROWSz, 256>>>(y2p, g2, be2, out);
}

// round 6
// speedup vs baseline: 2.0113x; 1.1754x over previous
#include <cuda_runtime.h>
#include <cuda_bf16.h>
#include <math.h>
#include <stdint.h>

// ---------------- Problem constants ----------------
#define Bz   16
#define Lz   1024
#define DMz  512
#define Hz   8
#define DKz  64
#define DVz  64
#define DHz  2048
#define Uz   35
#define BHz  (Bz*Hz)     // 128
#define ROWSz (Bz*Lz)    // 16384
#define EPSz 1e-5f

// ---------------- fp32 scratch ----------------
__device__ float g_Q[ROWSz*DMz];
__device__ float g_K[ROWSz*DMz];
__device__ float g_V[ROWSz*DMz];
__device__ float g_M[BHz*Lz];
__device__ int   g_Mtop[BHz*Uz];
__device__ int   g_rowmap[BHz*Lz];
__device__ float g_attn[(size_t)BHz*Uz*Lz];
__device__ float g_ctxrow[BHz*Uz*DVz];
__device__ float g_vmean[BHz*DVz];
__device__ float g_y[ROWSz*DMz];
__device__ float g_x1[ROWSz*DMz];
__device__ float g_y2[ROWSz*DMz];

// ---------------- bf16 split scratch ----------------
__device__ __nv_bfloat16 g_xh[ROWSz*DMz], g_xl[ROWSz*DMz];
__device__ __nv_bfloat16 g_ah[ROWSz*DMz], g_al[ROWSz*DMz];             // ctx, then x1 (never in-place)
__device__ __nv_bfloat16 g_hh[(size_t)ROWSz*DHz], g_hl[(size_t)ROWSz*DHz]; // relu(h) — DISTINCT from A
__device__ __nv_bfloat16 g_WqTh[DMz*DMz], g_WqTl[DMz*DMz];
__device__ __nv_bfloat16 g_WkTh[DMz*DMz], g_WkTl[DMz*DMz];
__device__ __nv_bfloat16 g_WvTh[DMz*DMz], g_WvTl[DMz*DMz];
__device__ __nv_bfloat16 g_WoTh[DMz*DMz], g_WoTl[DMz*DMz];
__device__ __nv_bfloat16 g_W1Th[DMz*DHz], g_W1Tl[DMz*DHz];
__device__ __nv_bfloat16 g_W2Th[DHz*DMz], g_W2Tl[DHz*DMz];

// ---------------- helpers ----------------
__device__ __forceinline__ void cp16(uint32_t s, const void* g) {
    asm volatile("cp.async.cg.shared.global [%0], [%1], 16;"
                 :: "r"(s), "l"(__cvta_generic_to_global(g)));
}
__device__ __forceinline__ void cp_commit() {
    asm volatile("cp.async.commit_group;" ::: "memory");
}
__device__ __forceinline__ void ldm_x4(uint32_t& r0, uint32_t& r1, uint32_t& r2, uint32_t& r3,
                                       uint32_t addr) {
    asm volatile("ldmatrix.sync.aligned.m8n8.x4.shared.b16 {%0,%1,%2,%3}, [%4];"
                 : "=r"(r0), "=r"(r1), "=r"(r2), "=r"(r3) : "r"(addr));
}
__device__ __forceinline__ void mma16816(float* c, const uint32_t* a, const uint32_t* b) {
    asm volatile("mma.sync.aligned.m16n8k16.row.col.f32.bf16.bf16.f32 "
                 "{%0,%1,%2,%3}, {%4,%5,%6,%7}, {%8,%9}, {%0,%1,%2,%3};"
                 : "+f"(c[0]), "+f"(c[1]), "+f"(c[2]), "+f"(c[3])
                 : "r"(a[0]), "r"(a[1]), "r"(a[2]), "r"(a[3]), "r"(b[0]), "r"(b[1]));
}

// ---------------- mma.sync bf16-split GEMM (fused 3-term) ----------------
// C = Ahi@Bhi + Ahi@Blo + Alo@Bhi (+bias) [+res | relu->bf16 hi/lo]
// A row-major [M][K] bf16 hi/lo; B K-major [N][K] bf16 hi/lo.
// Tile BM=BN=128, BK=32, 256 threads (8 warps of 64x32).
// Per k-tile: load all 4 operand tiles once; issue 3 MMA products.
// eop: 0 = bias, 1 = bias+res (fp32 C), 2 = bias+relu -> Chi/Clo bf16.
// NOTE: output buffers must NOT alias input A/B buffers (blocks race otherwise).
#define ROWB 80
#define TILEB (128 * ROWB)      // 10240 B per operand tile
#define STG4  (4 * TILEB)       // 40960 B per stage (Ahi|Alo|Bhi|Blo)
#define GEMM_SMEM (2 * STG4)    // 81920 B

__global__ void __launch_bounds__(256, 2)
gemm_bf16_kernel(const __nv_bfloat16* __restrict__ Ahi, const __nv_bfloat16* __restrict__ Alo,
                 const __nv_bfloat16* __restrict__ Bhi, const __nv_bfloat16* __restrict__ Blo,
                 const float* __restrict__ bias, const float* __restrict__ res,
                 float* __restrict__ C,
                 __nv_bfloat16* __restrict__ Chi, __nv_bfloat16* __restrict__ Clo,
                 int M, int N, int K, int eop)
{
    extern __shared__ __align__(16) char smem[];
    const uint32_t smem_u = (uint32_t)__cvta_generic_to_shared(smem);

    const int tid = threadIdx.x;
    const int wid = tid >> 5, lane = tid & 31;
    const int wm = (wid >> 2) * 64;      // warp m offset
    const int wn = (wid & 3) * 32;       // warp n offset
    const int g = lane >> 3, r = lane & 7;
    const int bm = blockIdx.y * 128;
    const int bn = blockIdx.x * 128;

    const int kt = K >> 5;

    float acc[4][4][4];
#pragma unroll
    for (int i = 0; i < 4; i++)
#pragma unroll
        for (int j = 0; j < 4; j++)
#pragma unroll
            for (int c = 0; c < 4; c++) acc[i][j][c] = 0.f;

    // 512 16B-chunks per tile; thread covers chunk tid (rows 0-63) and tid+256 (rows 64-127)
    const int ar = tid >> 2, ac = tid & 3;

    auto load_tile = [&](int it, int buf) {
        const int kk = it << 5;
        const uint32_t s0 = smem_u + buf * STG4;
        const size_t gaof = (size_t)(bm + ar) * K + kk + ac * 8;
        const size_t gbof = (size_t)(bn + ar) * K + kk + ac * 8;
        const size_t rowK64 = (size_t)64 * K;
        const uint32_t sof = ar * ROWB + ac * 16;
        cp16(s0 + 0 * TILEB + sof, Ahi + gaof);
        cp16(s0 + 0 * TILEB + sof + 64 * ROWB, Ahi + gaof + rowK64);
        cp16(s0 + 1 * TILEB + sof, Alo + gaof);
        cp16(s0 + 1 * TILEB + sof + 64 * ROWB, Alo + gaof + rowK64);
        cp16(s0 + 2 * TILEB + sof, Bhi + gbof);
        cp16(s0 + 2 * TILEB + sof + 64 * ROWB, Bhi + gbof + rowK64);
        cp16(s0 + 3 * TILEB + sof, Blo + gbof);
        cp16(s0 + 3 * TILEB + sof + 64 * ROWB, Blo + gbof + rowK64);
        cp_commit();
    };

    load_tile(0, 0);

    for (int it = 0; it < kt; it++) {
        const int buf = it & 1;
        if (it + 1 < kt) {
            load_tile(it + 1, buf ^ 1);
            asm volatile("cp.async.wait_group 1;" ::: "memory");
        } else {
            asm volatile("cp.async.wait_group 0;" ::: "memory");
        }
        __syncthreads();

        const uint32_t sAh = smem_u + buf * STG4;
        const uint32_t sAl = sAh + TILEB;
        const uint32_t sBh = sAh + 2 * TILEB;
        const uint32_t sBl = sAh + 3 * TILEB;
#pragma unroll
        for (int s = 0; s < 2; s++) {
            const int chkA = 2 * s + (g >> 1);
            const int chkB = 2 * s + (g & 1);
            const uint32_t aoff = (wm + ((g & 1) << 3) + r) * ROWB + chkA * 16;
            const uint32_t boff = (wn + ((g >> 1) << 3) + r) * ROWB + chkB * 16;

            uint32_t ah[4][4];
#pragma unroll
            for (int mf = 0; mf < 4; mf++)
                ldm_x4(ah[mf][0], ah[mf][1], ah[mf][2], ah[mf][3], sAh + aoff + mf * 16 * ROWB);
            uint32_t bh[4][2], bl[4][2];
#pragma unroll
            for (int ng = 0; ng < 2; ng++) {
                ldm_x4(bh[2 * ng][0], bh[2 * ng][1], bh[2 * ng + 1][0], bh[2 * ng + 1][1],
                       sBh + boff + ng * 16 * ROWB);
                ldm_x4(bl[2 * ng][0], bl[2 * ng][1], bl[2 * ng + 1][0], bl[2 * ng + 1][1],
                       sBl + boff + ng * 16 * ROWB);
            }
#pragma unroll
            for (int mf = 0; mf < 4; mf++)
#pragma unroll
                for (int nf = 0; nf < 4; nf++) {
                    mma16816(acc[mf][nf], ah[mf], bh[nf]);
                    mma16816(acc[mf][nf], ah[mf], bl[nf]);
                }
            // reuse ah registers for Alo fragments
#pragma unroll
            for (int mf = 0; mf < 4; mf++)
                ldm_x4(ah[mf][0], ah[mf][1], ah[mf][2], ah[mf][3], sAl + aoff + mf * 16 * ROWB);
#pragma unroll
            for (int mf = 0; mf < 4; mf++)
#pragma unroll
                for (int nf = 0; nf < 4; nf++)
                    mma16816(acc[mf][nf], ah[mf], bh[nf]);
        }
        __syncthreads();
    }

    // epilogue
    const int rl = lane >> 2, cl = (lane & 3) * 2;
#pragma unroll
    for (int mf = 0; mf < 4; mf++) {
        const int row0 = bm + wm + mf * 16 + rl;
#pragma unroll
        for (int nf = 0; nf < 4; nf++) {
            const int col = bn + wn + nf * 8 + cl;
            const float b0 = bias[col], b1 = bias[col + 1];
            float v0 = acc[mf][nf][0] + b0, v1 = acc[mf][nf][1] + b1;
            float v2 = acc[mf][nf][2] + b0, v3 = acc[mf][nf][3] + b1;
            if (eop == 1) {
                const float* r0 = res + (size_t)row0 * N + col;
                const float* r1 = res + (size_t)(row0 + 8) * N + col;
                v0 += r0[0]; v1 += r0[1]; v2 += r1[0]; v3 += r1[1];
            } else if (eop == 2) {
                v0 = fmaxf(v0, 0.f); v1 = fmaxf(v1, 0.f);
                v2 = fmaxf(v2, 0.f); v3 = fmaxf(v3, 0.f);
                __nv_bfloat162 h01, h23, l01, l23;
                h01.x = __float2bfloat16(v0); h01.y = __float2bfloat16(v1);
                h23.x = __float2bfloat16(v2); h23.y = __float2bfloat16(v3);
                l01.x = __float2bfloat16(v0 - __bfloat162float(h01.x));
                l01.y = __float2bfloat16(v1 - __bfloat162float(h01.y));
                l23.x = __float2bfloat16(v2 - __bfloat162float(h23.x));
                l23.y = __float2bfloat16(v3 - __bfloat162float(h23.y));
                *(__nv_bfloat162*)(Chi + (size_t)row0 * N + col) = h01;
                *(__nv_bfloat162*)(Chi + (size_t)(row0 + 8) * N + col) = h23;
                *(__nv_bfloat162*)(Clo + (size_t)row0 * N + col) = l01;
                *(__nv_bfloat162*)(Clo + (size_t)(row0 + 8) * N + col) = l23;
                continue;
            }
            *(float2*)(C + (size_t)row0 * N + col) = make_float2(v0, v1);
            *(float2*)(C + (size_t)(row0 + 8) * N + col) = make_float2(v2, v3);
        }
    }
}

// ---------------- fp32 -> bf16 hi/lo split (input x only) ----------------
__global__ void __launch_bounds__(256)
split_kernel(const float* __restrict__ src, __nv_bfloat16* __restrict__ hi,
             __nv_bfloat16* __restrict__ lo)
{
    const size_t i = (size_t)blockIdx.x * 256 + threadIdx.x;  // float4 index
    const float4 v = ((const float4*)src)[i];
    __nv_bfloat16 h0 = __float2bfloat16(v.x), h1 = __float2bfloat16(v.y);
    __nv_bfloat16 h2 = __float2bfloat16(v.z), h3 = __float2bfloat16(v.w);
    __nv_bfloat162 ha; ha.x = h0; ha.y = h1;
    __nv_bfloat162 hb; hb.x = h2; hb.y = h3;
    ((__nv_bfloat162*)hi)[i * 2 + 0] = ha;
    ((__nv_bfloat162*)hi)[i * 2 + 1] = hb;
    __nv_bfloat162 la, lb;
    la.x = __float2bfloat16(v.x - __bfloat162float(h0));
    la.y = __float2bfloat16(v.y - __bfloat162float(h1));
    lb.x = __float2bfloat16(v.z - __bfloat162float(h2));
    lb.y = __float2bfloat16(v.w - __bfloat162float(h3));
    ((__nv_bfloat162*)lo)[i * 2 + 0] = la;
    ((__nv_bfloat162*)lo)[i * 2 + 1] = lb;
}

// ---------------- weight transpose + split: W[K][N] -> WT[N][K] hi/lo ----------------
__global__ void __launch_bounds__(256)
tsplit_kernel(const float* __restrict__ src, __nv_bfloat16* __restrict__ hi,
              __nv_bfloat16* __restrict__ lo, int K, int N)
{
    __shared__ float tile[32][33];
    const int tx = threadIdx.x & 31, ty = threadIdx.x >> 5;
    const int n0 = blockIdx.x * 32, k0 = blockIdx.y * 32;
#pragma unroll
    for (int i = 0; i < 4; i++)
        tile[ty + 8 * i][tx] = src[(size_t)(k0 + ty + 8 * i) * N + n0 + tx];
    __syncthreads();
#pragma unroll
    for (int i = 0; i < 4; i++) {
        const int n = n0 + ty + 8 * i, k = k0 + tx;
        const float v = tile[tx][ty + 8 * i];
        const __nv_bfloat16 h = __float2bfloat16(v);
        hi[(size_t)n * K + k] = h;
        lo[(size_t)n * K + k] = __float2bfloat16(v - __bfloat162float(h));
    }
}

// ---------------- Sampled scores M = max_s(QK) - mean_s(QK) ----------------
__global__ void compute_m_kernel(const int* __restrict__ idx)
{
    const int gw = (blockIdx.x * blockDim.x + threadIdx.x) >> 5;
    const int lane = threadIdx.x & 31;
    if (gw >= BHz * Lz) return;
    const int l = gw & (Lz - 1);
    const int bh = gw >> 10;
    const int h = bh & (Hz - 1), b = bh >> 3;

    const float2* qrow = (const float2*)(g_Q + (size_t)(b * Lz + l) * DMz + h * DKz);
    const float2 q2 = qrow[lane];
    float mx = -INFINITY, sum = 0.f;
#pragma unroll 1
    for (int s = 0; s < Uz; s++) {
        const int j = idx[l * Uz + s];
        const float2 k2 = ((const float2*)(g_K + (size_t)(b * Lz + j) * DMz + h * DKz))[lane];
        float p = q2.x * k2.x + q2.y * k2.y;
#pragma unroll
        for (int o = 16; o; o >>= 1) p += __shfl_xor_sync(0xffffffffu, p, o);
        mx = fmaxf(mx, p);
        sum += p;
    }
    if (lane == 0) g_M[bh * Lz + l] = mx - sum * (1.0f / Uz);
}

// ---------------- top-35 per (b,h), tie -> smallest index ----------------
__global__ void __launch_bounds__(256) topk_kernel()
{
    const int bh = blockIdx.x;
    const int tid = threadIdx.x;
    __shared__ float vals[Lz];
    __shared__ float rv[256];
    __shared__ int   ri[256];

    for (int l = tid; l < Lz; l += 256) {
        vals[l] = g_M[bh * Lz + l];
        g_rowmap[bh * Lz + l] = -1;
    }
    __syncthreads();

    for (int u = 0; u < Uz; u++) {
        float best = -INFINITY; int bi = -1;
        for (int l = tid; l < Lz; l += 256) {
            float v = vals[l];
            if (v > best) { best = v; bi = l; }
        }
        rv[tid] = best; ri[tid] = bi;
        __syncthreads();
        for (int s = 128; s; s >>= 1) {
            if (tid < s) {
                float ov = rv[tid + s]; int oi = ri[tid + s];
                if (ov > rv[tid] ||
                    (ov == rv[tid] && (unsigned)oi < (unsigned)ri[tid])) {
                    rv[tid] = ov; ri[tid] = oi;
                }
            }
            __syncthreads();
        }
        if (tid == 0) {
            const int sel = ri[0];
            g_Mtop[bh * Uz + u] = sel;
            g_rowmap[bh * Lz + sel] = u;
            vals[sel] = -INFINITY;
        }
        __syncthreads();
    }
}

// ---------------- scores = Q_top @ K^T / 8 ----------------
__global__ void __launch_bounds__(256) scores_kernel()
{
    const int bh = blockIdx.x;
    const int b = bh >> 3, h = bh & (Hz - 1);
    const int tid = threadIdx.x;
    __shared__ float Qr[Uz * DKz];

    for (int i = tid; i < Uz * DKz; i += 256) {
        const int u = i / DKz, d = i - u * DKz;
        const int l = g_Mtop[bh * Uz + u];
        Qr[i] = g_Q[(size_t)(b * Lz + l) * DMz + h * DKz + d];
    }
    __syncthreads();

    for (int l = tid; l < Lz; l += 256) {
        float acc[Uz];
#pragma unroll
        for (int u = 0; u < Uz; u++) acc[u] = 0.f;
        const float* krow = g_K + (size_t)(b * Lz + l) * DMz + h * DKz;
#pragma unroll 4
        for (int d = 0; d < DKz; d++) {
            const float kd = krow[d];
#pragma unroll
            for (int u = 0; u < Uz; u++) acc[u] += kd * Qr[u * DKz + d];
        }
#pragma unroll
        for (int u = 0; u < Uz; u++)
            g_attn[((size_t)bh * Uz + u) * Lz + l] = acc[u] * 0.125f;
    }
}

// ---------------- row softmax over L ----------------
__global__ void __launch_bounds__(256) softmax_kernel()
{
    const int row = blockIdx.x;
    float* p = g_attn + (size_t)row * Lz;
    const int tid = threadIdx.x;
    __shared__ float red[256];

    float4 v = ((float4*)p)[tid];
    float m = fmaxf(fmaxf(v.x, v.y), fmaxf(v.z, v.w));
    red[tid] = m; __syncthreads();
    for (int s = 128; s; s >>= 1) { if (tid < s) red[tid] = fmaxf(red[tid], red[tid + s]); __syncthreads(); }
    m = red[0]; __syncthreads();

    v.x = __expf(v.x - m); v.y = __expf(v.y - m);
    v.z = __expf(v.z - m); v.w = __expf(v.w - m);
    red[tid] = v.x + v.y + v.z + v.w; __syncthreads();
    for (int s = 128; s; s >>= 1) { if (tid < s) red[tid] += red[tid + s]; __syncthreads(); }
    const float inv = 1.0f / red[0];
    v.x *= inv; v.y *= inv; v.z *= inv; v.w *= inv;
    ((float4*)p)[tid] = v;
}

// ---------------- context rows = attn @ V ----------------
__global__ void context_kernel()
{
    const int bhu = blockIdx.x;
    const int bh = bhu / Uz;
    const int b = bh >> 3, h = bh & (Hz - 1);
    const int d = threadIdx.x;
    const float* a = g_attn + (size_t)bhu * Lz;
    float acc = 0.f;
    const float* vbase = g_V + (size_t)(b * Lz) * DMz + h * DVz + d;
#pragma unroll 4
    for (int l = 0; l < Lz; l++) acc += a[l] * vbase[(size_t)l * DMz];
    g_ctxrow[bhu * DVz + d] = acc;
}

// ---------------- V mean over L ----------------
__global__ void vmean_kernel()
{
    const int bh = blockIdx.x;
    const int b = bh >> 3, h = bh & (Hz - 1);
    const int d = threadIdx.x;
    float acc = 0.f;
    const float* vbase = g_V + (size_t)(b * Lz) * DMz + h * DVz + d;
#pragma unroll 4
    for (int l = 0; l < Lz; l++) acc += vbase[(size_t)l * DMz];
    g_vmean[bh * DVz + d] = acc * (1.0f / Lz);
}

// ---------------- score output ----------------
__global__ void __launch_bounds__(256) write_scores_kernel(float* __restrict__ outp)
{
    const int row = blockIdx.x;
    const int bh = row >> 10;
    const int u = g_rowmap[row];
    float4* dst = (float4*)(outp + (size_t)row * Lz);
    const int tid = threadIdx.x;
    if (u < 0) {
        const float c = 1.0f / Lz;
        dst[tid] = make_float4(c, c, c, c);
    } else {
        const float4* src = (const float4*)(g_attn + ((size_t)bh * Uz + u) * Lz);
        dst[tid] = src[tid];
    }
}

// ---------------- assemble ctx -> bf16 hi/lo directly ----------------
__global__ void __launch_bounds__(256) ctx_assemble_kernel(__nv_bfloat16* __restrict__ hi,
                                                           __nv_bfloat16* __restrict__ lo)
{
    const size_t gidx = (size_t)blockIdx.x * 256 + threadIdx.x;
    const int row = (int)(gidx >> 9);
    const int c = (int)(gidx & 511);
    const int h = c >> 6, d = c & 63;
    const int b = row >> 10, l = row & (Lz - 1);
    const int bh = b * Hz + h;
    const int u = g_rowmap[bh * Lz + l];
    const float v = (u < 0) ? g_vmean[bh * DVz + d]
                            : g_ctxrow[(bh * Uz + u) * DVz + d];
    const __nv_bfloat16 hv = __float2bfloat16(v);
    hi[gidx] = hv;
    lo[gidx] = __float2bfloat16(v - __bfloat162float(hv));
}

// ---------------- LayerNorm (512), optional fused bf16 hi/lo output ----------------
__global__ void __launch_bounds__(256)
ln_kernel(const float* __restrict__ in, const float* __restrict__ g,
          const float* __restrict__ beta, float* __restrict__ out,
          __nv_bfloat16* __restrict__ hi, __nv_bfloat16* __restrict__ lo)
{
    const int row = blockIdx.x;
    const int tid = threadIdx.x;
    __shared__ float red[256];
    const float* r = in + (size_t)row * DMz;
    const float a = r[tid], b2 = r[tid + 256];

    red[tid] = a + b2; __syncthreads();
    for (int s = 128; s; s >>= 1) { if (tid < s) red[tid] += red[tid + s]; __syncthreads(); }
    const float mean = red[0] * (1.0f / DMz);
    __syncthreads();
    const float d0 = a - mean, d1 = b2 - mean;
    red[tid] = d0 * d0 + d1 * d1; __syncthreads();
    for (int s = 128; s; s >>= 1) { if (tid < s) red[tid] += red[tid + s]; __syncthreads(); }
    const float inv = rsqrtf(red[0] * (1.0f / DMz) + EPSz);
    const float o0 = g[tid]       * d0 * inv + beta[tid];
    const float o1 = g[tid + 256] * d1 * inv + beta[tid + 256];
    out[(size_t)row * DMz + tid]       = o0;
    out[(size_t)row * DMz + tid + 256] = o1;
    if (hi) {
        const __nv_bfloat16 h0 = __float2bfloat16(o0), h1 = __float2bfloat16(o1);
        hi[(size_t)row * DMz + tid]       = h0;
        hi[(size_t)row * DMz + tid + 256] = h1;
        lo[(size_t)row * DMz + tid]       = __float2bfloat16(o0 - __bfloat162float(h0));
        lo[(size_t)row * DMz + tid + 256] = __float2bfloat16(o1 - __bfloat162float(h1));
    }
}

// ---------------- launch ----------------
extern "C" void kernel_launch(void* const* d_in, const int* in_sizes, int n_in,
                              void* d_out, int out_size)
{
    const float* x   = (const float*)d_in[0];
    const float* Wq  = (const float*)d_in[1];
    const float* bq  = (const float*)d_in[2];
    const float* Wk  = (const float*)d_in[3];
    const float* bk  = (const float*)d_in[4];
    const float* Wv  = (const float*)d_in[5];
    const float* bv  = (const float*)d_in[6];
    const float* Wo  = (const float*)d_in[7];
    const float* bo  = (const float*)d_in[8];
    const float* g1  = (const float*)d_in[9];
    const float* be1 = (const float*)d_in[10];
    const float* W1  = (const float*)d_in[11];
    const float* bf1 = (const float*)d_in[12];
    const float* W2  = (const float*)d_in[13];
    const float* bf2 = (const float*)d_in[14];
    const float* g2  = (const float*)d_in[15];
    const float* be2 = (const float*)d_in[16];
    const int*   idx = (const int*)d_in[17];
    float* out = (float*)d_out;

    float *Qp, *Kp, *Vp, *yp, *x1p, *y2p;
    cudaGetSymbolAddress((void**)&Qp,   g_Q);
    cudaGetSymbolAddress((void**)&Kp,   g_K);
    cudaGetSymbolAddress((void**)&Vp,   g_V);
    cudaGetSymbolAddress((void**)&yp,   g_y);
    cudaGetSymbolAddress((void**)&x1p,  g_x1);
    cudaGetSymbolAddress((void**)&y2p,  g_y2);

    __nv_bfloat16 *xh, *xl, *ah, *al, *hh, *hl;
    __nv_bfloat16 *WqTh, *WqTl, *WkTh, *WkTl, *WvTh, *WvTl, *WoTh, *WoTl;
    __nv_bfloat16 *W1Th, *W1Tl, *W2Th, *W2Tl;
    cudaGetSymbolAddress((void**)&xh, g_xh);   cudaGetSymbolAddress((void**)&xl, g_xl);
    cudaGetSymbolAddress((void**)&ah, g_ah);   cudaGetSymbolAddress((void**)&al, g_al);
    cudaGetSymbolAddress((void**)&hh, g_hh);   cudaGetSymbolAddress((void**)&hl, g_hl);
    cudaGetSymbolAddress((void**)&WqTh, g_WqTh); cudaGetSymbolAddress((void**)&WqTl, g_WqTl);
    cudaGetSymbolAddress((void**)&WkTh, g_WkTh); cudaGetSymbolAddress((void**)&WkTl, g_WkTl);
    cudaGetSymbolAddress((void**)&WvTh, g_WvTh); cudaGetSymbolAddress((void**)&WvTl, g_WvTl);
    cudaGetSymbolAddress((void**)&WoTh, g_WoTh); cudaGetSymbolAddress((void**)&WoTl, g_WoTl);
    cudaGetSymbolAddress((void**)&W1Th, g_W1Th); cudaGetSymbolAddress((void**)&W1Tl, g_W1Tl);
    cudaGetSymbolAddress((void**)&W2Th, g_W2Th); cudaGetSymbolAddress((void**)&W2Tl, g_W2Tl);

    cudaFuncSetAttribute(gemm_bf16_kernel,
                         cudaFuncAttributeMaxDynamicSharedMemorySize, GEMM_SMEM);

    const dim3 gN512(4, 128);    // N=512 gemms: 128x128 tiles
    const dim3 gN2048(16, 128);  // N=2048 gemm

    // 0) conversions
    split_kernel<<<(ROWSz * DMz) / 1024, 256>>>(x, xh, xl);
    tsplit_kernel<<<dim3(16, 16), 256>>>(Wq, WqTh, WqTl, DMz, DMz);
    tsplit_kernel<<<dim3(16, 16), 256>>>(Wk, WkTh, WkTl, DMz, DMz);
    tsplit_kernel<<<dim3(16, 16), 256>>>(Wv, WvTh, WvTl, DMz, DMz);
    tsplit_kernel<<<dim3(16, 16), 256>>>(Wo, WoTh, WoTl, DMz, DMz);
    tsplit_kernel<<<dim3(64, 16), 256>>>(W1, W1Th, W1Tl, DMz, DHz);
    tsplit_kernel<<<dim3(16, 64), 256>>>(W2, W2Th, W2Tl, DHz, DMz);

    // 1) Q, K, V projections
    gemm_bf16_kernel<<<gN512, 256, GEMM_SMEM>>>(xh, xl, WqTh, WqTl, bq, nullptr, Qp, nullptr, nullptr, ROWSz, DMz, DMz, 0);
    gemm_bf16_kernel<<<gN512, 256, GEMM_SMEM>>>(xh, xl, WkTh, WkTl, bk, nullptr, Kp, nullptr, nullptr, ROWSz, DMz, DMz, 0);
    gemm_bf16_kernel<<<gN512, 256, GEMM_SMEM>>>(xh, xl, WvTh, WvTl, bv, nullptr, Vp, nullptr, nullptr, ROWSz, DMz, DMz, 0);

    // 2) ProbSparse attention
    compute_m_kernel<<<(BHz * Lz) / 8, 256>>>(idx);
    topk_kernel<<<BHz, 256>>>();
    scores_kernel<<<BHz, 256>>>();
    softmax_kernel<<<BHz * Uz, 256>>>();
    context_kernel<<<BHz * Uz, DVz>>>();
    vmean_kernel<<<BHz, DVz>>>();
    write_scores_kernel<<<BHz * Lz, 256>>>(out + (size_t)ROWSz * DMz);
    ctx_assemble_kernel<<<(ROWSz * DMz) / 256, 256>>>(ah, al);

    // 3) Wo projection + residual, LN1 (fused x1 split into ah/al — safe: GEMM done reading)
    gemm_bf16_kernel<<<gN512, 256, GEMM_SMEM>>>(ah, al, WoTh, WoTl, bo, x, yp, nullptr, nullptr, ROWSz, DMz, DMz, 1);
    ln_kernel<<<ROWSz, 256>>>(yp, g1, be1, x1p, ah, al);

    // 4) FFN: GEMM1 reads ah/al, writes relu(h) to DISTINCT hh/hl; GEMM2 consumes hh/hl
    gemm_bf16_kernel<<<gN2048, 256, GEMM_SMEM>>>(ah, al, W1Th, W1Tl, bf1, nullptr, nullptr, hh, hl, ROWSz, DHz, DMz, 2);
    gemm_bf16_kernel<<<gN512, 256, GEMM_SMEM>>>(hh, hl, W2Th, W2Tl, bf2, x1p, y2p, nullptr, nullptr, ROWSz, DMz, DHz, 1);
    ln_kernel<<<ROWSz, 256>>>(y2p, g2, be2, out, nullptr, nullptr);
}

// round 8
// speedup vs baseline: 2.0666x; 1.0275x over previous
#include <cuda_runtime.h>
#include <cuda_bf16.h>
#include <math.h>
#include <stdint.h>

// ---------------- Problem constants ----------------
#define Bz   16
#define Lz   1024
#define DMz  512
#define Hz   8
#define DKz  64
#define DVz  64
#define DHz  2048
#define Uz   35
#define BHz  (Bz*Hz)     // 128
#define ROWSz (Bz*Lz)    // 16384
#define EPSz 1e-5f

// ---------------- fp32 scratch ----------------
__device__ float g_Q[ROWSz*DMz];
__device__ float g_K[ROWSz*DMz];
__device__ float g_V[ROWSz*DMz];
__device__ float g_M[BHz*Lz];
__device__ int   g_Mtop[BHz*Uz];
__device__ int   g_rowmap[BHz*Lz];
__device__ float g_attn[(size_t)BHz*Uz*Lz];
__device__ float g_ctxrow[BHz*Uz*DVz];
__device__ float g_vmean[BHz*DVz];
__device__ float g_y[ROWSz*DMz];
__device__ float g_x1[ROWSz*DMz];
__device__ float g_y2[ROWSz*DMz];

// ---------------- bf16 split scratch ----------------
__device__ __nv_bfloat16 g_xh[ROWSz*DMz], g_xl[ROWSz*DMz];
__device__ __nv_bfloat16 g_ah[ROWSz*DMz], g_al[ROWSz*DMz];             // ctx, then x1
__device__ __nv_bfloat16 g_hh[(size_t)ROWSz*DHz], g_hl[(size_t)ROWSz*DHz]; // relu(h)
__device__ __nv_bfloat16 g_WqTh[DMz*DMz], g_WqTl[DMz*DMz];
__device__ __nv_bfloat16 g_WkTh[DMz*DMz], g_WkTl[DMz*DMz];
__device__ __nv_bfloat16 g_WvTh[DMz*DMz], g_WvTl[DMz*DMz];
__device__ __nv_bfloat16 g_WoTh[DMz*DMz], g_WoTl[DMz*DMz];
__device__ __nv_bfloat16 g_W1Th[DMz*DHz], g_W1Tl[DMz*DHz];
__device__ __nv_bfloat16 g_W2Th[DHz*DMz], g_W2Tl[DHz*DMz];

// ---------------- helpers ----------------
__device__ __forceinline__ void cp16(uint32_t s, const void* g) {
    asm volatile("cp.async.cg.shared.global [%0], [%1], 16;"
                 :: "r"(s), "l"(__cvta_generic_to_global(g)));
}
__device__ __forceinline__ void cp_commit() {
    asm volatile("cp.async.commit_group;" ::: "memory");
}
__device__ __forceinline__ void ldm_x4(uint32_t& r0, uint32_t& r1, uint32_t& r2, uint32_t& r3,
                                       uint32_t addr) {
    asm volatile("ldmatrix.sync.aligned.m8n8.x4.shared.b16 {%0,%1,%2,%3}, [%4];"
                 : "=r"(r0), "=r"(r1), "=r"(r2), "=r"(r3) : "r"(addr));
}
__device__ __forceinline__ void mma16816(float* c, const uint32_t* a, const uint32_t* b) {
    asm volatile("mma.sync.aligned.m16n8k16.row.col.f32.bf16.bf16.f32 "
                 "{%0,%1,%2,%3}, {%4,%5,%6,%7}, {%8,%9}, {%0,%1,%2,%3};"
                 : "+f"(c[0]), "+f"(c[1]), "+f"(c[2]), "+f"(c[3])
                 : "r"(a[0]), "r"(a[1]), "r"(a[2]), "r"(a[3]), "r"(b[0]), "r"(b[1]));
}

// ---------------- mma.sync bf16-split GEMM (fused 3-term, single-sync pipeline) ----------------
// C = Ahi@Bhi + Ahi@Blo + Alo@Bhi (+bias) [+res | relu->bf16 hi/lo]
// Tile BM=BN=128, BK=32, 256 threads (8 warps of 64x32). Double-buffered cp.async,
// ONE __syncthreads per k-tile: the barrier after wait_group both publishes tile `it`
// and proves all warps finished tile `it-1`, so prefetch into buf^1 after it is safe.
// ROWB=80: 16B-aligned rows (ldmatrix requirement) and (80/16)=5 odd -> conflict-free.
#define ROWB 80
#define TILEB (128 * ROWB)      // 10240 B per operand tile
#define STG4  (4 * TILEB)       // 40960 B per stage (Ahi|Alo|Bhi|Blo)
#define GEMM_SMEM (2 * STG4)    // 81920 B

__global__ void __launch_bounds__(256, 2)
gemm_bf16_kernel(const __nv_bfloat16* __restrict__ Ahi, const __nv_bfloat16* __restrict__ Alo,
                 const __nv_bfloat16* __restrict__ Bhi, const __nv_bfloat16* __restrict__ Blo,
                 const float* __restrict__ bias, const float* __restrict__ res,
                 float* __restrict__ C,
                 __nv_bfloat16* __restrict__ Chi, __nv_bfloat16* __restrict__ Clo,
                 int M, int N, int K, int eop)
{
    extern __shared__ __align__(16) char smem[];
    const uint32_t smem_u = (uint32_t)__cvta_generic_to_shared(smem);

    const int tid = threadIdx.x;
    const int wid = tid >> 5, lane = tid & 31;
    const int wm = (wid >> 2) * 64;
    const int wn = (wid & 3) * 32;
    const int g = lane >> 3, r = lane & 7;
    const int bm = blockIdx.y * 128;
    const int bn = blockIdx.x * 128;

    const int kt = K >> 5;

    float acc[4][4][4];
#pragma unroll
    for (int i = 0; i < 4; i++)
#pragma unroll
        for (int j = 0; j < 4; j++)
#pragma unroll
            for (int c = 0; c < 4; c++) acc[i][j][c] = 0.f;

    const int ar = tid >> 2, ac = tid & 3;   // 16B chunk coords (rows 0-63; +64 second half)

    auto load_tile = [&](int it, int buf) {
        const int kk = it << 5;
        const uint32_t s0 = smem_u + buf * STG4;
        const size_t gaof = (size_t)(bm + ar) * K + kk + ac * 8;
        const size_t gbof = (size_t)(bn + ar) * K + kk + ac * 8;
        const size_t rowK64 = (size_t)64 * K;
        const uint32_t sof = ar * ROWB + ac * 16;
        cp16(s0 + 0 * TILEB + sof, Ahi + gaof);
        cp16(s0 + 0 * TILEB + sof + 64 * ROWB, Ahi + gaof + rowK64);
        cp16(s0 + 1 * TILEB + sof, Alo + gaof);
        cp16(s0 + 1 * TILEB + sof + 64 * ROWB, Alo + gaof + rowK64);
        cp16(s0 + 2 * TILEB + sof, Bhi + gbof);
        cp16(s0 + 2 * TILEB + sof + 64 * ROWB, Bhi + gbof + rowK64);
        cp16(s0 + 3 * TILEB + sof, Blo + gbof);
        cp16(s0 + 3 * TILEB + sof + 64 * ROWB, Blo + gbof + rowK64);
        cp_commit();
    };

    load_tile(0, 0);

    for (int it = 0; it < kt; it++) {
        const int buf = it & 1;
        asm volatile("cp.async.wait_group 0;" ::: "memory");
        __syncthreads();   // tile `it` visible; all warps finished computing tile `it-1`

        if (it + 1 < kt) load_tile(it + 1, buf ^ 1);   // safe: buf^1 released by barrier

        const uint32_t sAh = smem_u + buf * STG4;
        const uint32_t sAl = sAh + TILEB;
        const uint32_t sBh = sAh + 2 * TILEB;
        const uint32_t sBl = sAh + 3 * TILEB;
#pragma unroll
        for (int s = 0; s < 2; s++) {
            const int chkA = 2 * s + (g >> 1);
            const int chkB = 2 * s + (g & 1);
            const uint32_t aoff = (wm + ((g & 1) << 3) + r) * ROWB + chkA * 16;
            const uint32_t boff = (wn + ((g >> 1) << 3) + r) * ROWB + chkB * 16;

            uint32_t ah[4][4];
#pragma unroll
            for (int mf = 0; mf < 4; mf++)
                ldm_x4(ah[mf][0], ah[mf][1], ah[mf][2], ah[mf][3], sAh + aoff + mf * 16 * ROWB);
            uint32_t bh[4][2], bl[4][2];
#pragma unroll
            for (int ng = 0; ng < 2; ng++) {
                ldm_x4(bh[2 * ng][0], bh[2 * ng][1], bh[2 * ng + 1][0], bh[2 * ng + 1][1],
                       sBh + boff + ng * 16 * ROWB);
                ldm_x4(bl[2 * ng][0], bl[2 * ng][1], bl[2 * ng + 1][0], bl[2 * ng + 1][1],
                       sBl + boff + ng * 16 * ROWB);
            }
#pragma unroll
            for (int mf = 0; mf < 4; mf++)
#pragma unroll
                for (int nf = 0; nf < 4; nf++) {
                    mma16816(acc[mf][nf], ah[mf], bh[nf]);
                    mma16816(acc[mf][nf], ah[mf], bl[nf]);
                }
#pragma unroll
            for (int mf = 0; mf < 4; mf++)
                ldm_x4(ah[mf][0], ah[mf][1], ah[mf][2], ah[mf][3], sAl + aoff + mf * 16 * ROWB);
#pragma unroll
            for (int mf = 0; mf < 4; mf++)
#pragma unroll
                for (int nf = 0; nf < 4; nf++)
                    mma16816(acc[mf][nf], ah[mf], bh[nf]);
        }
    }

    // epilogue
    const int rl = lane >> 2, cl = (lane & 3) * 2;
#pragma unroll
    for (int mf = 0; mf < 4; mf++) {
        const int row0 = bm + wm + mf * 16 + rl;
#pragma unroll
        for (int nf = 0; nf < 4; nf++) {
            const int col = bn + wn + nf * 8 + cl;
            const float b0 = bias[col], b1 = bias[col + 1];
            float v0 = acc[mf][nf][0] + b0, v1 = acc[mf][nf][1] + b1;
            float v2 = acc[mf][nf][2] + b0, v3 = acc[mf][nf][3] + b1;
            if (eop == 1) {
                const float* r0 = res + (size_t)row0 * N + col;
                const float* r1 = res + (size_t)(row0 + 8) * N + col;
                v0 += r0[0]; v1 += r0[1]; v2 += r1[0]; v3 += r1[1];
            } else if (eop == 2) {
                v0 = fmaxf(v0, 0.f); v1 = fmaxf(v1, 0.f);
                v2 = fmaxf(v2, 0.f); v3 = fmaxf(v3, 0.f);
                __nv_bfloat162 h01, h23, l01, l23;
                h01.x = __float2bfloat16(v0); h01.y = __float2bfloat16(v1);
                h23.x = __float2bfloat16(v2); h23.y = __float2bfloat16(v3);
                l01.x = __float2bfloat16(v0 - __bfloat162float(h01.x));
                l01.y = __float2bfloat16(v1 - __bfloat162float(h01.y));
                l23.x = __float2bfloat16(v2 - __bfloat162float(h23.x));
                l23.y = __float2bfloat16(v3 - __bfloat162float(h23.y));
                *(__nv_bfloat162*)(Chi + (size_t)row0 * N + col) = h01;
                *(__nv_bfloat162*)(Chi + (size_t)(row0 + 8) * N + col) = h23;
                *(__nv_bfloat162*)(Clo + (size_t)row0 * N + col) = l01;
                *(__nv_bfloat162*)(Clo + (size_t)(row0 + 8) * N + col) = l23;
                continue;
            }
            *(float2*)(C + (size_t)row0 * N + col) = make_float2(v0, v1);
            *(float2*)(C + (size_t)(row0 + 8) * N + col) = make_float2(v2, v3);
        }
    }
}

// ---------------- fp32 -> bf16 hi/lo split ----------------
__global__ void __launch_bounds__(256)
split_kernel(const float* __restrict__ src, __nv_bfloat16* __restrict__ hi,
             __nv_bfloat16* __restrict__ lo)
{
    const size_t i = (size_t)blockIdx.x * 256 + threadIdx.x;
    const float4 v = ((const float4*)src)[i];
    __nv_bfloat16 h0 = __float2bfloat16(v.x), h1 = __float2bfloat16(v.y);
    __nv_bfloat16 h2 = __float2bfloat16(v.z), h3 = __float2bfloat16(v.w);
    __nv_bfloat162 ha; ha.x = h0; ha.y = h1;
    __nv_bfloat162 hb; hb.x = h2; hb.y = h3;
    ((__nv_bfloat162*)hi)[i * 2 + 0] = ha;
    ((__nv_bfloat162*)hi)[i * 2 + 1] = hb;
    __nv_bfloat162 la, lb;
    la.x = __float2bfloat16(v.x - __bfloat162float(h0));
    la.y = __float2bfloat16(v.y - __bfloat162float(h1));
    lb.x = __float2bfloat16(v.z - __bfloat162float(h2));
    lb.y = __float2bfloat16(v.w - __bfloat162float(h3));
    ((__nv_bfloat162*)lo)[i * 2 + 0] = la;
    ((__nv_bfloat162*)lo)[i * 2 + 1] = lb;
}

// ---------------- weight transpose + split ----------------
__global__ void __launch_bounds__(256)
tsplit_kernel(const float* __restrict__ src, __nv_bfloat16* __restrict__ hi,
              __nv_bfloat16* __restrict__ lo, int K, int N)
{
    __shared__ float tile[32][33];
    const int tx = threadIdx.x & 31, ty = threadIdx.x >> 5;
    const int n0 = blockIdx.x * 32, k0 = blockIdx.y * 32;
#pragma unroll
    for (int i = 0; i < 4; i++)
        tile[ty + 8 * i][tx] = src[(size_t)(k0 + ty + 8 * i) * N + n0 + tx];
    __syncthreads();
#pragma unroll
    for (int i = 0; i < 4; i++) {
        const int n = n0 + ty + 8 * i, k = k0 + tx;
        const float v = tile[tx][ty + 8 * i];
        const __nv_bfloat16 h = __float2bfloat16(v);
        hi[(size_t)n * K + k] = h;
        lo[(size_t)n * K + k] = __float2bfloat16(v - __bfloat162float(h));
    }
}

// ---------------- Sampled scores M = max_s(QK) - mean_s(QK) ----------------
__global__ void compute_m_kernel(const int* __restrict__ idx)
{
    const int gw = (blockIdx.x * blockDim.x + threadIdx.x) >> 5;
    const int lane = threadIdx.x & 31;
    if (gw >= BHz * Lz) return;
    const int l = gw & (Lz - 1);
    const int bh = gw >> 10;
    const int h = bh & (Hz - 1), b = bh >> 3;

    const float2* qrow = (const float2*)(g_Q + (size_t)(b * Lz + l) * DMz + h * DKz);
    const float2 q2 = qrow[lane];
    float mx = -INFINITY, sum = 0.f;
#pragma unroll 1
    for (int s = 0; s < Uz; s++) {
        const int j = idx[l * Uz + s];
        const float2 k2 = ((const float2*)(g_K + (size_t)(b * Lz + j) * DMz + h * DKz))[lane];
        float p = q2.x * k2.x + q2.y * k2.y;
#pragma unroll
        for (int o = 16; o; o >>= 1) p += __shfl_xor_sync(0xffffffffu, p, o);
        mx = fmaxf(mx, p);
        sum += p;
    }
    if (lane == 0) g_M[bh * Lz + l] = mx - sum * (1.0f / Uz);
}

// ---------------- top-35 per (b,h): shfl reduction, tie -> smallest index ----------------
__global__ void __launch_bounds__(256) topk_kernel()
{
    const int bh = blockIdx.x;
    const int tid = threadIdx.x;
    const int wid = tid >> 5, lane = tid & 31;
    __shared__ float vals[Lz];
    __shared__ float wv[8];
    __shared__ int   wi[8];
    __shared__ int   ssel;

    for (int l = tid; l < Lz; l += 256) {
        vals[l] = g_M[bh * Lz + l];
        g_rowmap[bh * Lz + l] = -1;
    }
    __syncthreads();

    for (int u = 0; u < Uz; u++) {
        float best = -INFINITY; int bi = 0x7fffffff;
#pragma unroll
        for (int c = 0; c < 4; c++) {
            const int l = tid + c * 256;
            const float v = vals[l];
            if (v > best) { best = v; bi = l; }
        }
#pragma unroll
        for (int o = 16; o; o >>= 1) {
            const float ov = __shfl_xor_sync(0xffffffffu, best, o);
            const int   oi = __shfl_xor_sync(0xffffffffu, bi, o);
            if (ov > best || (ov == best && oi < bi)) { best = ov; bi = oi; }
        }
        if (lane == 0) { wv[wid] = best; wi[wid] = bi; }
        __syncthreads();
        if (tid == 0) {
            float fb = wv[0]; int fi = wi[0];
#pragma unroll
            for (int w = 1; w < 8; w++) {
                if (wv[w] > fb || (wv[w] == fb && wi[w] < fi)) { fb = wv[w]; fi = wi[w]; }
            }
            g_Mtop[bh * Uz + u] = fi;
            g_rowmap[bh * Lz + fi] = u;
            ssel = fi;
            vals[fi] = -INFINITY;
        }
        __syncthreads();
    }
}

// ---------------- scores = Q_top @ K^T / 8 ----------------
__global__ void __launch_bounds__(256) scores_kernel()
{
    const int bh = blockIdx.x;
    const int b = bh >> 3, h = bh & (Hz - 1);
    const int tid = threadIdx.x;
    __shared__ float Qr[Uz * DKz];

    for (int i = tid; i < Uz * DKz; i += 256) {
        const int u = i / DKz, d = i - u * DKz;
        const int l = g_Mtop[bh * Uz + u];
        Qr[i] = g_Q[(size_t)(b * Lz + l) * DMz + h * DKz + d];
    }
    __syncthreads();

    for (int l = tid; l < Lz; l += 256) {
        float acc[Uz];
#pragma unroll
        for (int u = 0; u < Uz; u++) acc[u] = 0.f;
        const float* krow = g_K + (size_t)(b * Lz + l) * DMz + h * DKz;
#pragma unroll 4
        for (int d = 0; d < DKz; d++) {
            const float kd = krow[d];
#pragma unroll
            for (int u = 0; u < Uz; u++) acc[u] += kd * Qr[u * DKz + d];
        }
#pragma unroll
        for (int u = 0; u < Uz; u++)
            g_attn[((size_t)bh * Uz + u) * Lz + l] = acc[u] * 0.125f;
    }
}

// ---------------- row softmax over L ----------------
__global__ void __launch_bounds__(256) softmax_kernel()
{
    const int row = blockIdx.x;
    float* p = g_attn + (size_t)row * Lz;
    const int tid = threadIdx.x;
    __shared__ float red[256];

    float4 v = ((float4*)p)[tid];
    float m = fmaxf(fmaxf(v.x, v.y), fmaxf(v.z, v.w));
    red[tid] = m; __syncthreads();
    for (int s = 128; s; s >>= 1) { if (tid < s) red[tid] = fmaxf(red[tid], red[tid + s]); __syncthreads(); }
    m = red[0]; __syncthreads();

    v.x = __expf(v.x - m); v.y = __expf(v.y - m);
    v.z = __expf(v.z - m); v.w = __expf(v.w - m);
    red[tid] = v.x + v.y + v.z + v.w; __syncthreads();
    for (int s = 128; s; s >>= 1) { if (tid < s) red[tid] += red[tid + s]; __syncthreads(); }
    const float inv = 1.0f / red[0];
    v.x *= inv; v.y *= inv; v.z *= inv; v.w *= inv;
    ((float4*)p)[tid] = v;
}

// ---------------- context: block per (b,h), V streamed once ----------------
__global__ void __launch_bounds__(256) context_kernel()
{
    const int bh = blockIdx.x;
    const int b = bh >> 3, h = bh & (Hz - 1);
    const int t = threadIdx.x;
    const int d = t & 63, ug = t >> 6;          // ug in 0..3
    __shared__ float sat[Uz][129];

    float acc[9];
#pragma unroll
    for (int k = 0; k < 9; k++) acc[k] = 0.f;

    for (int c = 0; c < 8; c++) {
        for (int i = t; i < Uz * 128; i += 256) {
            const int u = i >> 7, li = i & 127;
            sat[u][li] = g_attn[((size_t)bh * Uz + u) * Lz + c * 128 + li];
        }
        __syncthreads();
        const float* vb = g_V + (size_t)(b * Lz + c * 128) * DMz + h * DVz + d;
#pragma unroll 4
        for (int i = 0; i < 128; i++) {
            const float v = vb[(size_t)i * DMz];
#pragma unroll
            for (int k = 0; k < 9; k++) {
                const int u = ug + 4 * k;
                if (u < Uz) acc[k] += sat[u][i] * v;
            }
        }
        __syncthreads();
    }
#pragma unroll
    for (int k = 0; k < 9; k++) {
        const int u = ug + 4 * k;
        if (u < Uz) g_ctxrow[(bh * Uz + u) * DVz + d] = acc[k];
    }
}

// ---------------- V mean over L ----------------
__global__ void vmean_kernel()
{
    const int bh = blockIdx.x;
    const int b = bh >> 3, h = bh & (Hz - 1);
    const int d = threadIdx.x;
    float acc = 0.f;
    const float* vbase = g_V + (size_t)(b * Lz) * DMz + h * DVz + d;
#pragma unroll 4
    for (int l = 0; l < Lz; l++) acc += vbase[(size_t)l * DMz];
    g_vmean[bh * DVz + d] = acc * (1.0f / Lz);
}

// ---------------- score output ----------------
__global__ void __launch_bounds__(256) write_scores_kernel(float* __restrict__ outp)
{
    const int row = blockIdx.x;
    const int bh = row >> 10;
    const int u = g_rowmap[row];
    float4* dst = (float4*)(outp + (size_t)row * Lz);
    const int tid = threadIdx.x;
    if (u < 0) {
        const float c = 1.0f / Lz;
        dst[tid] = make_float4(c, c, c, c);
    } else {
        const float4* src = (const float4*)(g_attn + ((size_t)bh * Uz + u) * Lz);
        dst[tid] = src[tid];
    }
}

// ---------------- assemble ctx -> bf16 hi/lo ----------------
__global__ void __launch_bounds__(256) ctx_assemble_kernel(__nv_bfloat16* __restrict__ hi,
                                                           __nv_bfloat16* __restrict__ lo)
{
    const size_t gidx = (size_t)blockIdx.x * 256 + threadIdx.x;
    const int row = (int)(gidx >> 9);
    const int c = (int)(gidx & 511);
    const int h = c >> 6, d = c & 63;
    const int b = row >> 10, l = row & (Lz - 1);
    const int bh = b * Hz + h;
    const int u = g_rowmap[bh * Lz + l];
    const float v = (u < 0) ? g_vmean[bh * DVz + d]
                            : g_ctxrow[(bh * Uz + u) * DVz + d];
    const __nv_bfloat16 hv = __float2bfloat16(v);
    hi[gidx] = hv;
    lo[gidx] = __float2bfloat16(v - __bfloat162float(hv));
}

// ---------------- LayerNorm (512), optional fused bf16 hi/lo output ----------------
__global__ void __launch_bounds__(256)
ln_kernel(const float* __restrict__ in, const float* __restrict__ g,
          const float* __restrict__ beta, float* __restrict__ out,
          __nv_bfloat16* __restrict__ hi, __nv_bfloat16* __restrict__ lo)
{
    const int row = blockIdx.x;
    const int tid = threadIdx.x;
    __shared__ float red[256];
    const float* r = in + (size_t)row * DMz;
    const float a = r[tid], b2 = r[tid + 256];

    red[tid] = a + b2; __syncthreads();
    for (int s = 128; s; s >>= 1) { if (tid < s) red[tid] += red[tid + s]; __syncthreads(); }
    const float mean = red[0] * (1.0f / DMz);
    __syncthreads();
    const float d0 = a - mean, d1 = b2 - mean;
    red[tid] = d0 * d0 + d1 * d1; __syncthreads();
    for (int s = 128; s; s >>= 1) { if (tid < s) red[tid] += red[tid + s]; __syncthreads(); }
    const float inv = rsqrtf(red[0] * (1.0f / DMz) + EPSz);
    const float o0 = g[tid]       * d0 * inv + beta[tid];
    const float o1 = g[tid + 256] * d1 * inv + beta[tid + 256];
    out[(size_t)row * DMz + tid]       = o0;
    out[(size_t)row * DMz + tid + 256] = o1;
    if (hi) {
        const __nv_bfloat16 h0 = __float2bfloat16(o0), h1 = __float2bfloat16(o1);
        hi[(size_t)row * DMz + tid]       = h0;
        hi[(size_t)row * DMz + tid + 256] = h1;
        lo[(size_t)row * DMz + tid]       = __float2bfloat16(o0 - __bfloat162float(h0));
        lo[(size_t)row * DMz + tid + 256] = __float2bfloat16(o1 - __bfloat162float(h1));
    }
}

// ---------------- launch ----------------
extern "C" void kernel_launch(void* const* d_in, const int* in_sizes, int n_in,
                              void* d_out, int out_size)
{
    const float* x   = (const float*)d_in[0];
    const float* Wq  = (const float*)d_in[1];
    const float* bq  = (const float*)d_in[2];
    const float* Wk  = (const float*)d_in[3];
    const float* bk  = (const float*)d_in[4];
    const float* Wv  = (const float*)d_in[5];
    const float* bv  = (const float*)d_in[6];
    const float* Wo  = (const float*)d_in[7];
    const float* bo  = (const float*)d_in[8];
    const float* g1  = (const float*)d_in[9];
    const float* be1 = (const float*)d_in[10];
    const float* W1  = (const float*)d_in[11];
    const float* bf1 = (const float*)d_in[12];
    const float* W2  = (const float*)d_in[13];
    const float* bf2 = (const float*)d_in[14];
    const float* g2  = (const float*)d_in[15];
    const float* be2 = (const float*)d_in[16];
    const int*   idx = (const int*)d_in[17];
    float* out = (float*)d_out;

    float *Qp, *Kp, *Vp, *yp, *x1p, *y2p;
    cudaGetSymbolAddress((void**)&Qp,   g_Q);
    cudaGetSymbolAddress((void**)&Kp,   g_K);
    cudaGetSymbolAddress((void**)&Vp,   g_V);
    cudaGetSymbolAddress((void**)&yp,   g_y);
    cudaGetSymbolAddress((void**)&x1p,  g_x1);
    cudaGetSymbolAddress((void**)&y2p,  g_y2);

    __nv_bfloat16 *xh, *xl, *ah, *al, *hh, *hl;
    __nv_bfloat16 *WqTh, *WqTl, *WkTh, *WkTl, *WvTh, *WvTl, *WoTh, *WoTl;
    __nv_bfloat16 *W1Th, *W1Tl, *W2Th, *W2Tl;
    cudaGetSymbolAddress((void**)&xh, g_xh);   cudaGetSymbolAddress((void**)&xl, g_xl);
    cudaGetSymbolAddress((void**)&ah, g_ah);   cudaGetSymbolAddress((void**)&al, g_al);
    cudaGetSymbolAddress((void**)&hh, g_hh);   cudaGetSymbolAddress((void**)&hl, g_hl);
    cudaGetSymbolAddress((void**)&WqTh, g_WqTh); cudaGetSymbolAddress((void**)&WqTl, g_WqTl);
    cudaGetSymbolAddress((void**)&WkTh, g_WkTh); cudaGetSymbolAddress((void**)&WkTl, g_WkTl);
    cudaGetSymbolAddress((void**)&WvTh, g_WvTh); cudaGetSymbolAddress((void**)&WvTl, g_WvTl);
    cudaGetSymbolAddress((void**)&WoTh, g_WoTh); cudaGetSymbolAddress((void**)&WoTl, g_WoTl);
    cudaGetSymbolAddress((void**)&W1Th, g_W1Th); cudaGetSymbolAddress((void**)&W1Tl, g_W1Tl);
    cudaGetSymbolAddress((void**)&W2Th, g_W2Th); cudaGetSymbolAddress((void**)&W2Tl, g_W2Tl);

    cudaFuncSetAttribute(gemm_bf16_kernel,
                         cudaFuncAttributeMaxDynamicSharedMemorySize, GEMM_SMEM);

    const dim3 gN512(4, 128);
    const dim3 gN2048(16, 128);

    // 0) conversions
    split_kernel<<<(ROWSz * DMz) / 1024, 256>>>(x, xh, xl);
    tsplit_kernel<<<dim3(16, 16), 256>>>(Wq, WqTh, WqTl, DMz, DMz);
    tsplit_kernel<<<dim3(16, 16), 256>>>(Wk, WkTh, WkTl, DMz, DMz);
    tsplit_kernel<<<dim3(16, 16), 256>>>(Wv, WvTh, WvTl, DMz, DMz);
    tsplit_kernel<<<dim3(16, 16), 256>>>(Wo, WoTh, WoTl, DMz, DMz);
    tsplit_kernel<<<dim3(64, 16), 256>>>(W1, W1Th, W1Tl, DMz, DHz);
    tsplit_kernel<<<dim3(16, 64), 256>>>(W2, W2Th, W2Tl, DHz, DMz);

    // 1) Q, K, V projections
    gemm_bf16_kernel<<<gN512, 256, GEMM_SMEM>>>(xh, xl, WqTh, WqTl, bq, nullptr, Qp, nullptr, nullptr, ROWSz, DMz, DMz, 0);
    gemm_bf16_kernel<<<gN512, 256, GEMM_SMEM>>>(xh, xl, WkTh, WkTl, bk, nullptr, Kp, nullptr, nullptr, ROWSz, DMz, DMz, 0);
    gemm_bf16_kernel<<<gN512, 256, GEMM_SMEM>>>(xh, xl, WvTh, WvTl, bv, nullptr, Vp, nullptr, nullptr, ROWSz, DMz, DMz, 0);

    // 2) ProbSparse attention
    compute_m_kernel<<<(BHz * Lz) / 8, 256>>>(idx);
    topk_kernel<<<BHz, 256>>>();
    scores_kernel<<<BHz, 256>>>();
    softmax_kernel<<<BHz * Uz, 256>>>();
    context_kernel<<<BHz, 256>>>();
    vmean_kernel<<<BHz, DVz>>>();
    write_scores_kernel<<<BHz * Lz, 256>>>(out + (size_t)ROWSz * DMz);
    ctx_assemble_kernel<<<(ROWSz * DMz) / 256, 256>>>(ah, al);

    // 3) Wo projection + residual, LN1 (fused x1 split)
    gemm_bf16_kernel<<<gN512, 256, GEMM_SMEM>>>(ah, al, WoTh, WoTl, bo, x, yp, nullptr, nullptr, ROWSz, DMz, DMz, 1);
    ln_kernel<<<ROWSz, 256>>>(yp, g1, be1, x1p, ah, al);

    // 4) FFN
    gemm_bf16_kernel<<<gN2048, 256, GEMM_SMEM>>>(ah, al, W1Th, W1Tl, bf1, nullptr, nullptr, hh, hl, ROWSz, DHz, DMz, 2);
    gemm_bf16_kernel<<<gN512, 256, GEMM_SMEM>>>(hh, hl, W2Th, W2Tl, bf2, x1p, y2p, nullptr, nullptr, ROWSz, DMz, DHz, 1);
    ln_kernel<<<ROWSz, 256>>>(y2p, g2, be2, out, nullptr, nullptr);
}

// round 9
// speedup vs baseline: 2.7488x; 1.3301x over previous
#include <cuda_runtime.h>
#include <cuda_bf16.h>
#include <cuda_fp16.h>
#include <math.h>
#include <stdint.h>

// ---------------- Problem constants ----------------
#define Bz   16
#define Lz   1024
#define DMz  512
#define Hz   8
#define DKz  64
#define DVz  64
#define DHz  2048
#define Uz   35
#define BHz  (Bz*Hz)     // 128
#define ROWSz (Bz*Lz)    // 16384
#define EPSz 1e-5f

// ---------------- fp32 scratch ----------------
__device__ float g_Q[ROWSz*DMz];
__device__ float g_K[ROWSz*DMz];
__device__ float g_V[ROWSz*DMz];
__device__ float g_M[BHz*Lz];
__device__ int   g_Mtop[BHz*Uz];
__device__ int   g_rowmap[BHz*Lz];
__device__ float g_attn[(size_t)BHz*Uz*Lz];
__device__ float g_ctxrow[BHz*Uz*DVz];
__device__ float g_vmean[BHz*DVz];
__device__ float g_y[ROWSz*DMz];
__device__ float g_x1[ROWSz*DMz];
__device__ float g_y2[ROWSz*DMz];

// ---------------- bf16 split scratch (Q/K path, 3-term) ----------------
__device__ __nv_bfloat16 g_xh[ROWSz*DMz], g_xl[ROWSz*DMz];
__device__ __nv_bfloat16 g_WqTh[DMz*DMz], g_WqTl[DMz*DMz];
__device__ __nv_bfloat16 g_WkTh[DMz*DMz], g_WkTl[DMz*DMz];

// ---------------- fp16 scratch (V/Wo/FFN path, single-pass) ----------------
__device__ __half g_xf[ROWSz*DMz];
__device__ __half g_cf[ROWSz*DMz];       // ctx
__device__ __half g_x1f[ROWSz*DMz];      // x1
__device__ __half g_hf[(size_t)ROWSz*DHz]; // relu(h)
__device__ __half g_WvTf[DMz*DMz];
__device__ __half g_WoTf[DMz*DMz];
__device__ __half g_W1Tf[DMz*DHz];
__device__ __half g_W2Tf[DHz*DMz];

// ---------------- helpers ----------------
__device__ __forceinline__ void cp16(uint32_t s, const void* g) {
    asm volatile("cp.async.cg.shared.global [%0], [%1], 16;"
                 :: "r"(s), "l"(__cvta_generic_to_global(g)));
}
__device__ __forceinline__ void cp_commit() {
    asm volatile("cp.async.commit_group;" ::: "memory");
}
__device__ __forceinline__ void ldm_x4(uint32_t& r0, uint32_t& r1, uint32_t& r2, uint32_t& r3,
                                       uint32_t addr) {
    asm volatile("ldmatrix.sync.aligned.m8n8.x4.shared.b16 {%0,%1,%2,%3}, [%4];"
                 : "=r"(r0), "=r"(r1), "=r"(r2), "=r"(r3) : "r"(addr));
}
template<bool ISBF16>
__device__ __forceinline__ void mma_t(float* c, const uint32_t* a, const uint32_t* b) {
    if constexpr (ISBF16)
        asm volatile("mma.sync.aligned.m16n8k16.row.col.f32.bf16.bf16.f32 "
                     "{%0,%1,%2,%3}, {%4,%5,%6,%7}, {%8,%9}, {%0,%1,%2,%3};"
                     : "+f"(c[0]), "+f"(c[1]), "+f"(c[2]), "+f"(c[3])
                     : "r"(a[0]), "r"(a[1]), "r"(a[2]), "r"(a[3]), "r"(b[0]), "r"(b[1]));
    else
        asm volatile("mma.sync.aligned.m16n8k16.row.col.f32.f16.f16.f32 "
                     "{%0,%1,%2,%3}, {%4,%5,%6,%7}, {%8,%9}, {%0,%1,%2,%3};"
                     : "+f"(c[0]), "+f"(c[1]), "+f"(c[2]), "+f"(c[3])
                     : "r"(a[0]), "r"(a[1]), "r"(a[2]), "r"(a[3]), "r"(b[0]), "r"(b[1]));
}

// ---------------- mma.sync GEMM, templated <TERMS, ISBF16> ----------------
// TERMS=3 (bf16 split): C = Ahi@Bhi + Ahi@Blo + Alo@Bhi
// TERMS=1 (fp16 single): C = Ahi@Bhi
// A row-major [M][K]; B K-major [N][K]. Tile BM=BN=128, BK=32, 256 threads.
// eop: 0 bias (fp32 C), 1 bias+res (fp32 C), 2 bias+relu -> half Chi.
#define ROWB 80
#define TILEB (128 * ROWB)      // 10240 B per operand tile

template<int TERMS, bool ISBF16>
__global__ void __launch_bounds__(256, 2)
gemm_kernel(const uint16_t* __restrict__ Ahi, const uint16_t* __restrict__ Alo,
            const uint16_t* __restrict__ Bhi, const uint16_t* __restrict__ Blo,
            const float* __restrict__ bias, const float* __restrict__ res,
            float* __restrict__ C, uint16_t* __restrict__ Chi,
            int M, int N, int K, int eop)
{
    constexpr int NT = (TERMS == 3) ? 4 : 2;          // tiles per stage
    constexpr uint32_t STG = NT * TILEB;
    extern __shared__ __align__(16) char smem[];
    const uint32_t smem_u = (uint32_t)__cvta_generic_to_shared(smem);

    const int tid = threadIdx.x;
    const int wid = tid >> 5, lane = tid & 31;
    const int wm = (wid >> 2) * 64;
    const int wn = (wid & 3) * 32;
    const int g = lane >> 3, r = lane & 7;
    const int bm = blockIdx.y * 128;
    const int bn = blockIdx.x * 128;

    const int kt = K >> 5;

    float acc[4][4][4];
#pragma unroll
    for (int i = 0; i < 4; i++)
#pragma unroll
        for (int j = 0; j < 4; j++)
#pragma unroll
            for (int c = 0; c < 4; c++) acc[i][j][c] = 0.f;

    const int ar = tid >> 2, ac = tid & 3;

    auto load_tile = [&](int it, int buf) {
        const int kk = it << 5;
        const uint32_t s0 = smem_u + buf * STG;
        const size_t gaof = (size_t)(bm + ar) * K + kk + ac * 8;
        const size_t gbof = (size_t)(bn + ar) * K + kk + ac * 8;
        const size_t rowK64 = (size_t)64 * K;
        const uint32_t sof = ar * ROWB + ac * 16;
        cp16(s0 + sof, Ahi + gaof);
        cp16(s0 + sof + 64 * ROWB, Ahi + gaof + rowK64);
        if constexpr (TERMS == 3) {
            cp16(s0 + TILEB + sof, Alo + gaof);
            cp16(s0 + TILEB + sof + 64 * ROWB, Alo + gaof + rowK64);
            cp16(s0 + 2 * TILEB + sof, Bhi + gbof);
            cp16(s0 + 2 * TILEB + sof + 64 * ROWB, Bhi + gbof + rowK64);
            cp16(s0 + 3 * TILEB + sof, Blo + gbof);
            cp16(s0 + 3 * TILEB + sof + 64 * ROWB, Blo + gbof + rowK64);
        } else {
            cp16(s0 + TILEB + sof, Bhi + gbof);
            cp16(s0 + TILEB + sof + 64 * ROWB, Bhi + gbof + rowK64);
        }
        cp_commit();
    };

    load_tile(0, 0);

    for (int it = 0; it < kt; it++) {
        const int buf = it & 1;
        asm volatile("cp.async.wait_group 0;" ::: "memory");
        __syncthreads();

        if (it + 1 < kt) load_tile(it + 1, buf ^ 1);

        const uint32_t sAh = smem_u + buf * STG;
        const uint32_t sBh = sAh + ((TERMS == 3) ? 2 : 1) * TILEB;
#pragma unroll
        for (int s = 0; s < 2; s++) {
            const int chkA = 2 * s + (g >> 1);
            const int chkB = 2 * s + (g & 1);
            const uint32_t aoff = (wm + ((g & 1) << 3) + r) * ROWB + chkA * 16;
            const uint32_t boff = (wn + ((g >> 1) << 3) + r) * ROWB + chkB * 16;

            uint32_t ah[4][4];
#pragma unroll
            for (int mf = 0; mf < 4; mf++)
                ldm_x4(ah[mf][0], ah[mf][1], ah[mf][2], ah[mf][3], sAh + aoff + mf * 16 * ROWB);
            uint32_t bh[4][2];
#pragma unroll
            for (int ng = 0; ng < 2; ng++)
                ldm_x4(bh[2 * ng][0], bh[2 * ng][1], bh[2 * ng + 1][0], bh[2 * ng + 1][1],
                       sBh + boff + ng * 16 * ROWB);

            if constexpr (TERMS == 3) {
                const uint32_t sAl = sAh + TILEB;
                const uint32_t sBl = sAh + 3 * TILEB;
                uint32_t bl[4][2];
#pragma unroll
                for (int ng = 0; ng < 2; ng++)
                    ldm_x4(bl[2 * ng][0], bl[2 * ng][1], bl[2 * ng + 1][0], bl[2 * ng + 1][1],
                           sBl + boff + ng * 16 * ROWB);
#pragma unroll
                for (int mf = 0; mf < 4; mf++)
#pragma unroll
                    for (int nf = 0; nf < 4; nf++) {
                        mma_t<ISBF16>(acc[mf][nf], ah[mf], bh[nf]);
                        mma_t<ISBF16>(acc[mf][nf], ah[mf], bl[nf]);
                    }
#pragma unroll
                for (int mf = 0; mf < 4; mf++)
                    ldm_x4(ah[mf][0], ah[mf][1], ah[mf][2], ah[mf][3], sAl + aoff + mf * 16 * ROWB);
#pragma unroll
                for (int mf = 0; mf < 4; mf++)
#pragma unroll
                    for (int nf = 0; nf < 4; nf++)
                        mma_t<ISBF16>(acc[mf][nf], ah[mf], bh[nf]);
            } else {
#pragma unroll
                for (int mf = 0; mf < 4; mf++)
#pragma unroll
                    for (int nf = 0; nf < 4; nf++)
                        mma_t<ISBF16>(acc[mf][nf], ah[mf], bh[nf]);
            }
        }
    }

    // epilogue
    const int rl = lane >> 2, cl = (lane & 3) * 2;
#pragma unroll
    for (int mf = 0; mf < 4; mf++) {
        const int row0 = bm + wm + mf * 16 + rl;
#pragma unroll
        for (int nf = 0; nf < 4; nf++) {
            const int col = bn + wn + nf * 8 + cl;
            const float b0 = bias[col], b1 = bias[col + 1];
            float v0 = acc[mf][nf][0] + b0, v1 = acc[mf][nf][1] + b1;
            float v2 = acc[mf][nf][2] + b0, v3 = acc[mf][nf][3] + b1;
            if (eop == 1) {
                const float* r0 = res + (size_t)row0 * N + col;
                const float* r1 = res + (size_t)(row0 + 8) * N + col;
                v0 += r0[0]; v1 += r0[1]; v2 += r1[0]; v3 += r1[1];
            } else if (eop == 2) {
                v0 = fmaxf(v0, 0.f); v1 = fmaxf(v1, 0.f);
                v2 = fmaxf(v2, 0.f); v3 = fmaxf(v3, 0.f);
                *(__half2*)(Chi + (size_t)row0 * N + col)       = __floats2half2_rn(v0, v1);
                *(__half2*)(Chi + (size_t)(row0 + 8) * N + col) = __floats2half2_rn(v2, v3);
                continue;
            }
            *(float2*)(C + (size_t)row0 * N + col) = make_float2(v0, v1);
            *(float2*)(C + (size_t)(row0 + 8) * N + col) = make_float2(v2, v3);
        }
    }
}

// ---------------- fp32 -> bf16 hi/lo split ----------------
__global__ void __launch_bounds__(256)
split_kernel(const float* __restrict__ src, __nv_bfloat16* __restrict__ hi,
             __nv_bfloat16* __restrict__ lo)
{
    const size_t i = (size_t)blockIdx.x * 256 + threadIdx.x;
    const float4 v = ((const float4*)src)[i];
    __nv_bfloat16 h0 = __float2bfloat16(v.x), h1 = __float2bfloat16(v.y);
    __nv_bfloat16 h2 = __float2bfloat16(v.z), h3 = __float2bfloat16(v.w);
    __nv_bfloat162 ha; ha.x = h0; ha.y = h1;
    __nv_bfloat162 hb; hb.x = h2; hb.y = h3;
    ((__nv_bfloat162*)hi)[i * 2 + 0] = ha;
    ((__nv_bfloat162*)hi)[i * 2 + 1] = hb;
    __nv_bfloat162 la, lb;
    la.x = __float2bfloat16(v.x - __bfloat162float(h0));
    la.y = __float2bfloat16(v.y - __bfloat162float(h1));
    lb.x = __float2bfloat16(v.z - __bfloat162float(h2));
    lb.y = __float2bfloat16(v.w - __bfloat162float(h3));
    ((__nv_bfloat162*)lo)[i * 2 + 0] = la;
    ((__nv_bfloat162*)lo)[i * 2 + 1] = lb;
}

// ---------------- fp32 -> fp16 convert ----------------
__global__ void __launch_bounds__(256)
splitf_kernel(const float* __restrict__ src, __half* __restrict__ dst)
{
    const size_t i = (size_t)blockIdx.x * 256 + threadIdx.x;
    const float4 v = ((const float4*)src)[i];
    ((__half2*)dst)[i * 2 + 0] = __floats2half2_rn(v.x, v.y);
    ((__half2*)dst)[i * 2 + 1] = __floats2half2_rn(v.z, v.w);
}

// ---------------- weight transpose + bf16 hi/lo split ----------------
__global__ void __launch_bounds__(256)
tsplit_kernel(const float* __restrict__ src, __nv_bfloat16* __restrict__ hi,
              __nv_bfloat16* __restrict__ lo, int K, int N)
{
    __shared__ float tile[32][33];
    const int tx = threadIdx.x & 31, ty = threadIdx.x >> 5;
    const int n0 = blockIdx.x * 32, k0 = blockIdx.y * 32;
#pragma unroll
    for (int i = 0; i < 4; i++)
        tile[ty + 8 * i][tx] = src[(size_t)(k0 + ty + 8 * i) * N + n0 + tx];
    __syncthreads();
#pragma unroll
    for (int i = 0; i < 4; i++) {
        const int n = n0 + ty + 8 * i, k = k0 + tx;
        const float v = tile[tx][ty + 8 * i];
        const __nv_bfloat16 h = __float2bfloat16(v);
        hi[(size_t)n * K + k] = h;
        lo[(size_t)n * K + k] = __float2bfloat16(v - __bfloat162float(h));
    }
}

// ---------------- weight transpose -> fp16 ----------------
__global__ void __launch_bounds__(256)
tsplitf_kernel(const float* __restrict__ src, __half* __restrict__ dst, int K, int N)
{
    __shared__ float tile[32][33];
    const int tx = threadIdx.x & 31, ty = threadIdx.x >> 5;
    const int n0 = blockIdx.x * 32, k0 = blockIdx.y * 32;
#pragma unroll
    for (int i = 0; i < 4; i++)
        tile[ty + 8 * i][tx] = src[(size_t)(k0 + ty + 8 * i) * N + n0 + tx];
    __syncthreads();
#pragma unroll
    for (int i = 0; i < 4; i++) {
        const int n = n0 + ty + 8 * i, k = k0 + tx;
        dst[(size_t)n * K + k] = __float2half(tile[tx][ty + 8 * i]);
    }
}

// ---------------- Sampled scores M = max_s(QK) - mean_s(QK) ----------------
__global__ void compute_m_kernel(const int* __restrict__ idx)
{
    const int gw = (blockIdx.x * blockDim.x + threadIdx.x) >> 5;
    const int lane = threadIdx.x & 31;
    if (gw >= BHz * Lz) return;
    const int l = gw & (Lz - 1);
    const int bh = gw >> 10;
    const int h = bh & (Hz - 1), b = bh >> 3;

    const float2* qrow = (const float2*)(g_Q + (size_t)(b * Lz + l) * DMz + h * DKz);
    const float2 q2 = qrow[lane];
    float mx = -INFINITY, sum = 0.f;
#pragma unroll 1
    for (int s = 0; s < Uz; s++) {
        const int j = idx[l * Uz + s];
        const float2 k2 = ((const float2*)(g_K + (size_t)(b * Lz + j) * DMz + h * DKz))[lane];
        float p = q2.x * k2.x + q2.y * k2.y;
#pragma unroll
        for (int o = 16; o; o >>= 1) p += __shfl_xor_sync(0xffffffffu, p, o);
        mx = fmaxf(mx, p);
        sum += p;
    }
    if (lane == 0) g_M[bh * Lz + l] = mx - sum * (1.0f / Uz);
}

// ---------------- top-35 per (b,h): shfl reduction, tie -> smallest index ----------------
__global__ void __launch_bounds__(256) topk_kernel()
{
    const int bh = blockIdx.x;
    const int tid = threadIdx.x;
    const int wid = tid >> 5, lane = tid & 31;
    __shared__ float vals[Lz];
    __shared__ float wv[8];
    __shared__ int   wi[8];

    for (int l = tid; l < Lz; l += 256) {
        vals[l] = g_M[bh * Lz + l];
        g_rowmap[bh * Lz + l] = -1;
    }
    __syncthreads();

    for (int u = 0; u < Uz; u++) {
        float best = -INFINITY; int bi = 0x7fffffff;
#pragma unroll
        for (int c = 0; c < 4; c++) {
            const int l = tid + c * 256;
            const float v = vals[l];
            if (v > best) { best = v; bi = l; }
        }
#pragma unroll
        for (int o = 16; o; o >>= 1) {
            const float ov = __shfl_xor_sync(0xffffffffu, best, o);
            const int   oi = __shfl_xor_sync(0xffffffffu, bi, o);
            if (ov > best || (ov == best && oi < bi)) { best = ov; bi = oi; }
        }
        if (lane == 0) { wv[wid] = best; wi[wid] = bi; }
        __syncthreads();
        if (tid == 0) {
            float fb = wv[0]; int fi = wi[0];
#pragma unroll
            for (int w = 1; w < 8; w++) {
                if (wv[w] > fb || (wv[w] == fb && wi[w] < fi)) { fb = wv[w]; fi = wi[w]; }
            }
            g_Mtop[bh * Uz + u] = fi;
            g_rowmap[bh * Lz + fi] = u;
            vals[fi] = -INFINITY;
        }
        __syncthreads();
    }
}

// ---------------- scores = Q_top @ K^T / 8 ----------------
__global__ void __launch_bounds__(256) scores_kernel()
{
    const int bh = blockIdx.x;
    const int b = bh >> 3, h = bh & (Hz - 1);
    const int tid = threadIdx.x;
    __shared__ float Qr[Uz * DKz];

    for (int i = tid; i < Uz * DKz; i += 256) {
        const int u = i / DKz, d = i - u * DKz;
        const int l = g_Mtop[bh * Uz + u];
        Qr[i] = g_Q[(size_t)(b * Lz + l) * DMz + h * DKz + d];
    }
    __syncthreads();

    for (int l = tid; l < Lz; l += 256) {
        float acc[Uz];
#pragma unroll
        for (int u = 0; u < Uz; u++) acc[u] = 0.f;
        const float* krow = g_K + (size_t)(b * Lz + l) * DMz + h * DKz;
#pragma unroll 4
        for (int d = 0; d < DKz; d++) {
            const float kd = krow[d];
#pragma unroll
            for (int u = 0; u < Uz; u++) acc[u] += kd * Qr[u * DKz + d];
        }
#pragma unroll
        for (int u = 0; u < Uz; u++)
            g_attn[((size_t)bh * Uz + u) * Lz + l] = acc[u] * 0.125f;
    }
}

// ---------------- row softmax over L ----------------
__global__ void __launch_bounds__(256) softmax_kernel()
{
    const int row = blockIdx.x;
    float* p = g_attn + (size_t)row * Lz;
    const int tid = threadIdx.x;
    __shared__ float red[256];

    float4 v = ((float4*)p)[tid];
    float m = fmaxf(fmaxf(v.x, v.y), fmaxf(v.z, v.w));
    red[tid] = m; __syncthreads();
    for (int s = 128; s; s >>= 1) { if (tid < s) red[tid] = fmaxf(red[tid], red[tid + s]); __syncthreads(); }
    m = red[0]; __syncthreads();

    v.x = __expf(v.x - m); v.y = __expf(v.y - m);
    v.z = __expf(v.z - m); v.w = __expf(v.w - m);
    red[tid] = v.x + v.y + v.z + v.w; __syncthreads();
    for (int s = 128; s; s >>= 1) { if (tid < s) red[tid] += red[tid + s]; __syncthreads(); }
    const float inv = 1.0f / red[0];
    v.x *= inv; v.y *= inv; v.z *= inv; v.w *= inv;
    ((float4*)p)[tid] = v;
}

// ---------------- context: block per (b,h), V streamed once ----------------
__global__ void __launch_bounds__(256) context_kernel()
{
    const int bh = blockIdx.x;
    const int b = bh >> 3, h = bh & (Hz - 1);
    const int t = threadIdx.x;
    const int d = t & 63, ug = t >> 6;
    __shared__ float sat[Uz][129];

    float acc[9];
#pragma unroll
    for (int k = 0; k < 9; k++) acc[k] = 0.f;

    for (int c = 0; c < 8; c++) {
        for (int i = t; i < Uz * 128; i += 256) {
            const int u = i >> 7, li = i & 127;
            sat[u][li] = g_attn[((size_t)bh * Uz + u) * Lz + c * 128 + li];
        }
        __syncthreads();
        const float* vb = g_V + (size_t)(b * Lz + c * 128) * DMz + h * DVz + d;
#pragma unroll 4
        for (int i = 0; i < 128; i++) {
            const float v = vb[(size_t)i * DMz];
#pragma unroll
            for (int k = 0; k < 9; k++) {
                const int u = ug + 4 * k;
                if (u < Uz) acc[k] += sat[u][i] * v;
            }
        }
        __syncthreads();
    }
#pragma unroll
    for (int k = 0; k < 9; k++) {
        const int u = ug + 4 * k;
        if (u < Uz) g_ctxrow[(bh * Uz + u) * DVz + d] = acc[k];
    }
}

// ---------------- V mean over L ----------------
__global__ void vmean_kernel()
{
    const int bh = blockIdx.x;
    const int b = bh >> 3, h = bh & (Hz - 1);
    const int d = threadIdx.x;
    float acc = 0.f;
    const float* vbase = g_V + (size_t)(b * Lz) * DMz + h * DVz + d;
#pragma unroll 4
    for (int l = 0; l < Lz; l++) acc += vbase[(size_t)l * DMz];
    g_vmean[bh * DVz + d] = acc * (1.0f / Lz);
}

// ---------------- score output ----------------
__global__ void __launch_bounds__(256) write_scores_kernel(float* __restrict__ outp)
{
    const int row = blockIdx.x;
    const int bh = row >> 10;
    const int u = g_rowmap[row];
    float4* dst = (float4*)(outp + (size_t)row * Lz);
    const int tid = threadIdx.x;
    if (u < 0) {
        const float c = 1.0f / Lz;
        dst[tid] = make_float4(c, c, c, c);
    } else {
        const float4* src = (const float4*)(g_attn + ((size_t)bh * Uz + u) * Lz);
        dst[tid] = src[tid];
    }
}

// ---------------- assemble ctx -> fp16 ----------------
__global__ void __launch_bounds__(256) ctx_assemble_kernel(__half* __restrict__ dst)
{
    const size_t gidx = (size_t)blockIdx.x * 256 + threadIdx.x;
    const int row = (int)(gidx >> 9);
    const int c = (int)(gidx & 511);
    const int h = c >> 6, d = c & 63;
    const int b = row >> 10, l = row & (Lz - 1);
    const int bh = b * Hz + h;
    const int u = g_rowmap[bh * Lz + l];
    const float v = (u < 0) ? g_vmean[bh * DVz + d]
                            : g_ctxrow[(bh * Uz + u) * DVz + d];
    dst[gidx] = __float2half(v);
}

// ---------------- LayerNorm (512), optional fused fp16 output ----------------
__global__ void __launch_bounds__(256)
ln_kernel(const float* __restrict__ in, const float* __restrict__ g,
          const float* __restrict__ beta, float* __restrict__ out,
          __half* __restrict__ outf)
{
    const int row = blockIdx.x;
    const int tid = threadIdx.x;
    __shared__ float red[256];
    const float* r = in + (size_t)row * DMz;
    const float a = r[tid], b2 = r[tid + 256];

    red[tid] = a + b2; __syncthreads();
    for (int s = 128; s; s >>= 1) { if (tid < s) red[tid] += red[tid + s]; __syncthreads(); }
    const float mean = red[0] * (1.0f / DMz);
    __syncthreads();
    const float d0 = a - mean, d1 = b2 - mean;
    red[tid] = d0 * d0 + d1 * d1; __syncthreads();
    for (int s = 128; s; s >>= 1) { if (tid < s) red[tid] += red[tid + s]; __syncthreads(); }
    const float inv = rsqrtf(red[0] * (1.0f / DMz) + EPSz);
    const float o0 = g[tid]       * d0 * inv + beta[tid];
    const float o1 = g[tid + 256] * d1 * inv + beta[tid + 256];
    out[(size_t)row * DMz + tid]       = o0;
    out[(size_t)row * DMz + tid + 256] = o1;
    if (outf) {
        outf[(size_t)row * DMz + tid]       = __float2half(o0);
        outf[(size_t)row * DMz + tid + 256] = __float2half(o1);
    }
}

// ---------------- launch ----------------
extern "C" void kernel_launch(void* const* d_in, const int* in_sizes, int n_in,
                              void* d_out, int out_size)
{
    const float* x   = (const float*)d_in[0];
    const float* Wq  = (const float*)d_in[1];
    const float* bq  = (const float*)d_in[2];
    const float* Wk  = (const float*)d_in[3];
    const float* bk  = (const float*)d_in[4];
    const float* Wv  = (const float*)d_in[5];
    const float* bv  = (const float*)d_in[6];
    const float* Wo  = (const float*)d_in[7];
    const float* bo  = (const float*)d_in[8];
    const float* g1  = (const float*)d_in[9];
    const float* be1 = (const float*)d_in[10];
    const float* W1  = (const float*)d_in[11];
    const float* bf1 = (const float*)d_in[12];
    const float* W2  = (const float*)d_in[13];
    const float* bf2 = (const float*)d_in[14];
    const float* g2  = (const float*)d_in[15];
    const float* be2 = (const float*)d_in[16];
    const int*   idx = (const int*)d_in[17];
    float* out = (float*)d_out;

    float *Qp, *Kp, *Vp, *yp, *x1p, *y2p;
    cudaGetSymbolAddress((void**)&Qp,   g_Q);
    cudaGetSymbolAddress((void**)&Kp,   g_K);
    cudaGetSymbolAddress((void**)&Vp,   g_V);
    cudaGetSymbolAddress((void**)&yp,   g_y);
    cudaGetSymbolAddress((void**)&x1p,  g_x1);
    cudaGetSymbolAddress((void**)&y2p,  g_y2);

    __nv_bfloat16 *xh, *xl, *WqTh, *WqTl, *WkTh, *WkTl;
    __half *xf, *cf, *x1f, *hf, *WvTf, *WoTf, *W1Tf, *W2Tf;
    cudaGetSymbolAddress((void**)&xh, g_xh);     cudaGetSymbolAddress((void**)&xl, g_xl);
    cudaGetSymbolAddress((void**)&WqTh, g_WqTh); cudaGetSymbolAddress((void**)&WqTl, g_WqTl);
    cudaGetSymbolAddress((void**)&WkTh, g_WkTh); cudaGetSymbolAddress((void**)&WkTl, g_WkTl);
    cudaGetSymbolAddress((void**)&xf, g_xf);     cudaGetSymbolAddress((void**)&cf, g_cf);
    cudaGetSymbolAddress((void**)&x1f, g_x1f);   cudaGetSymbolAddress((void**)&hf, g_hf);
    cudaGetSymbolAddress((void**)&WvTf, g_WvTf); cudaGetSymbolAddress((void**)&WoTf, g_WoTf);
    cudaGetSymbolAddress((void**)&W1Tf, g_W1Tf); cudaGetSymbolAddress((void**)&W2Tf, g_W2Tf);

    const int SM3 = 2 * 4 * TILEB;   // 81920
    const int SM1 = 2 * 2 * TILEB;   // 40960
    cudaFuncSetAttribute(gemm_kernel<3, true>,
                         cudaFuncAttributeMaxDynamicSharedMemorySize, SM3);
    cudaFuncSetAttribute(gemm_kernel<1, false>,
                         cudaFuncAttributeMaxDynamicSharedMemorySize, SM1);

    const dim3 gN512(4, 128);
    const dim3 gN2048(16, 128);

    // conversions needed for QKV first (ordered so launch #6 = GEMM Q for ncu)
    split_kernel<<<(ROWSz * DMz) / 1024, 256>>>(x, xh, xl);                 // 1
    tsplit_kernel<<<dim3(16, 16), 256>>>(Wq, WqTh, WqTl, DMz, DMz);         // 2
    tsplit_kernel<<<dim3(16, 16), 256>>>(Wk, WkTh, WkTl, DMz, DMz);         // 3
    splitf_kernel<<<(ROWSz * DMz) / 1024, 256>>>(x, xf);                    // 4
    tsplitf_kernel<<<dim3(16, 16), 256>>>(Wv, WvTf, DMz, DMz);              // 5

    // QKV projections
    gemm_kernel<3, true><<<gN512, 256, SM3>>>((const uint16_t*)xh, (const uint16_t*)xl,
        (const uint16_t*)WqTh, (const uint16_t*)WqTl, bq, nullptr, Qp, nullptr, ROWSz, DMz, DMz, 0);  // 6 (ncu)
    gemm_kernel<3, true><<<gN512, 256, SM3>>>((const uint16_t*)xh, (const uint16_t*)xl,
        (const uint16_t*)WkTh, (const uint16_t*)WkTl, bk, nullptr, Kp, nullptr, ROWSz, DMz, DMz, 0);  // 7
    gemm_kernel<1, false><<<gN512, 256, SM1>>>((const uint16_t*)xf, nullptr,
        (const uint16_t*)WvTf, nullptr, bv, nullptr, Vp, nullptr, ROWSz, DMz, DMz, 0);                // 8

    // remaining weight conversions
    tsplitf_kernel<<<dim3(16, 16), 256>>>(Wo, WoTf, DMz, DMz);
    tsplitf_kernel<<<dim3(64, 16), 256>>>(W1, W1Tf, DMz, DHz);
    tsplitf_kernel<<<dim3(16, 64), 256>>>(W2, W2Tf, DHz, DMz);

    // ProbSparse attention
    compute_m_kernel<<<(BHz * Lz) / 8, 256>>>(idx);
    topk_kernel<<<BHz, 256>>>();
    scores_kernel<<<BHz, 256>>>();
    softmax_kernel<<<BHz * Uz, 256>>>();
    context_kernel<<<BHz, 256>>>();
    vmean_kernel<<<BHz, DVz>>>();
    write_scores_kernel<<<BHz * Lz, 256>>>(out + (size_t)ROWSz * DMz);
    ctx_assemble_kernel<<<(ROWSz * DMz) / 256, 256>>>(cf);

    // Wo projection + residual, LN1 (fused fp16 x1)
    gemm_kernel<1, false><<<gN512, 256, SM1>>>((const uint16_t*)cf, nullptr,
        (const uint16_t*)WoTf, nullptr, bo, x, yp, nullptr, ROWSz, DMz, DMz, 1);
    ln_kernel<<<ROWSz, 256>>>(yp, g1, be1, x1p, x1f);

    // FFN
    gemm_kernel<1, false><<<gN2048, 256, SM1>>>((const uint16_t*)x1f, nullptr,
        (const uint16_t*)W1Tf, nullptr, bf1, nullptr, nullptr, (uint16_t*)hf, ROWSz, DHz, DMz, 2);
    gemm_kernel<1, false><<<gN512, 256, SM1>>>((const uint16_t*)hf, nullptr,
        (const uint16_t*)W2Tf, nullptr, bf2, x1p, y2p, nullptr, ROWSz, DMz, DHz, 1);
    ln_kernel<<<ROWSz, 256>>>(y2p, g2, be2, out, nullptr);
}

// round 11
// speedup vs baseline: 2.9527x; 1.0742x over previous
#include <cuda_runtime.h>
#include <cuda_bf16.h>
#include <cuda_fp16.h>
#include <math.h>
#include <stdint.h>

// ---------------- Problem constants ----------------
#define Bz   16
#define Lz   1024
#define DMz  512
#define Hz   8
#define DKz  64
#define DVz  64
#define DHz  2048
#define Uz   35
#define BHz  (Bz*Hz)     // 128
#define ROWSz (Bz*Lz)    // 16384
#define EPSz 1e-5f

// ---------------- fp32 scratch ----------------
__device__ float g_Q[ROWSz*DMz];
__device__ float g_K[ROWSz*DMz];
__device__ float g_V[ROWSz*DMz];
__device__ float g_M[BHz*Lz];
__device__ int   g_Mtop[BHz*Uz];
__device__ int   g_rowmap[BHz*Lz];
__device__ float g_attn[(size_t)BHz*Uz*Lz];
__device__ float g_ctxrow[BHz*Uz*DVz];
__device__ float g_vmean[BHz*DVz];
__device__ float g_y[ROWSz*DMz];
__device__ float g_x1[ROWSz*DMz];
__device__ float g_y2[ROWSz*DMz];

// ---------------- bf16 split scratch (Q/K path, 3-term) ----------------
__device__ __nv_bfloat16 g_xh[ROWSz*DMz], g_xl[ROWSz*DMz];
__device__ __nv_bfloat16 g_WqTh[DMz*DMz], g_WqTl[DMz*DMz];
__device__ __nv_bfloat16 g_WkTh[DMz*DMz], g_WkTl[DMz*DMz];

// ---------------- fp16 scratch (V/Wo/FFN path, single-pass) ----------------
__device__ __half g_xf[ROWSz*DMz];
__device__ __half g_cf[ROWSz*DMz];
__device__ __half g_x1f[ROWSz*DMz];
__device__ __half g_hf[(size_t)ROWSz*DHz];
__device__ __half g_WvTf[DMz*DMz];
__device__ __half g_WoTf[DMz*DMz];
__device__ __half g_W1Tf[DMz*DHz];
__device__ __half g_W2Tf[DHz*DMz];

// ---------------- helpers ----------------
__device__ __forceinline__ void cp16(uint32_t s, const void* g) {
    asm volatile("cp.async.cg.shared.global [%0], [%1], 16;"
                 :: "r"(s), "l"(__cvta_generic_to_global(g)));
}
__device__ __forceinline__ void cp_commit() {
    asm volatile("cp.async.commit_group;" ::: "memory");
}
__device__ __forceinline__ void ldm_x4(uint32_t& r0, uint32_t& r1, uint32_t& r2, uint32_t& r3,
                                       uint32_t addr) {
    asm volatile("ldmatrix.sync.aligned.m8n8.x4.shared.b16 {%0,%1,%2,%3}, [%4];"
                 : "=r"(r0), "=r"(r1), "=r"(r2), "=r"(r3) : "r"(addr));
}
template<bool ISBF16>
__device__ __forceinline__ void mma_t(float* c, const uint32_t* a, const uint32_t* b) {
    if constexpr (ISBF16)
        asm volatile("mma.sync.aligned.m16n8k16.row.col.f32.bf16.bf16.f32 "
                     "{%0,%1,%2,%3}, {%4,%5,%6,%7}, {%8,%9}, {%0,%1,%2,%3};"
                     : "+f"(c[0]), "+f"(c[1]), "+f"(c[2]), "+f"(c[3])
                     : "r"(a[0]), "r"(a[1]), "r"(a[2]), "r"(a[3]), "r"(b[0]), "r"(b[1]));
    else
        asm volatile("mma.sync.aligned.m16n8k16.row.col.f32.f16.f16.f32 "
                     "{%0,%1,%2,%3}, {%4,%5,%6,%7}, {%8,%9}, {%0,%1,%2,%3};"
                     : "+f"(c[0]), "+f"(c[1]), "+f"(c[2]), "+f"(c[3])
                     : "r"(a[0]), "r"(a[1]), "r"(a[2]), "r"(a[3]), "r"(b[0]), "r"(b[1]));
}

// ---------------- mma.sync GEMM, templated <TERMS, ISBF16>, optional score-fill ----------------
#define ROWB 80
#define TILEB (128 * ROWB)

template<int TERMS, bool ISBF16>
__global__ void __launch_bounds__(256, 2)
gemm_kernel(const uint16_t* __restrict__ Ahi, const uint16_t* __restrict__ Alo,
            const uint16_t* __restrict__ Bhi, const uint16_t* __restrict__ Blo,
            const float* __restrict__ bias, const float* __restrict__ res,
            float* __restrict__ C, uint16_t* __restrict__ Chi,
            float* __restrict__ fillp, int fillPerBlk,
            int M, int N, int K, int eop)
{
    constexpr int NT = (TERMS == 3) ? 4 : 2;
    constexpr uint32_t STG = NT * TILEB;
    extern __shared__ __align__(16) char smem[];
    const uint32_t smem_u = (uint32_t)__cvta_generic_to_shared(smem);

    const int tid = threadIdx.x;
    const int wid = tid >> 5, lane = tid & 31;
    const int wm = (wid >> 2) * 64;
    const int wn = (wid & 3) * 32;
    const int g = lane >> 3, r = lane & 7;
    const int bm = blockIdx.y * 128;
    const int bn = blockIdx.x * 128;

    const int kt = K >> 5;

    float acc[4][4][4];
#pragma unroll
    for (int i = 0; i < 4; i++)
#pragma unroll
        for (int j = 0; j < 4; j++)
#pragma unroll
            for (int c = 0; c < 4; c++) acc[i][j][c] = 0.f;

    const int ar = tid >> 2, ac = tid & 3;

    auto load_tile = [&](int it, int buf) {
        const int kk = it << 5;
        const uint32_t s0 = smem_u + buf * STG;
        const size_t gaof = (size_t)(bm + ar) * K + kk + ac * 8;
        const size_t gbof = (size_t)(bn + ar) * K + kk + ac * 8;
        const size_t rowK64 = (size_t)64 * K;
        const uint32_t sof = ar * ROWB + ac * 16;
        cp16(s0 + sof, Ahi + gaof);
        cp16(s0 + sof + 64 * ROWB, Ahi + gaof + rowK64);
        if constexpr (TERMS == 3) {
            cp16(s0 + TILEB + sof, Alo + gaof);
            cp16(s0 + TILEB + sof + 64 * ROWB, Alo + gaof + rowK64);
            cp16(s0 + 2 * TILEB + sof, Bhi + gbof);
            cp16(s0 + 2 * TILEB + sof + 64 * ROWB, Bhi + gbof + rowK64);
            cp16(s0 + 3 * TILEB + sof, Blo + gbof);
            cp16(s0 + 3 * TILEB + sof + 64 * ROWB, Blo + gbof + rowK64);
        } else {
            cp16(s0 + TILEB + sof, Bhi + gbof);
            cp16(s0 + TILEB + sof + 64 * ROWB, Bhi + gbof + rowK64);
        }
        cp_commit();
    };

    load_tile(0, 0);

    for (int it = 0; it < kt; it++) {
        const int buf = it & 1;
        asm volatile("cp.async.wait_group 0;" ::: "memory");
        __syncthreads();

        if (it + 1 < kt) load_tile(it + 1, buf ^ 1);

        const uint32_t sAh = smem_u + buf * STG;
        const uint32_t sBh = sAh + ((TERMS == 3) ? 2 : 1) * TILEB;
#pragma unroll
        for (int s = 0; s < 2; s++) {
            const int chkA = 2 * s + (g >> 1);
            const int chkB = 2 * s + (g & 1);
            const uint32_t aoff = (wm + ((g & 1) << 3) + r) * ROWB + chkA * 16;
            const uint32_t boff = (wn + ((g >> 1) << 3) + r) * ROWB + chkB * 16;

            uint32_t ah[4][4];
#pragma unroll
            for (int mf = 0; mf < 4; mf++)
                ldm_x4(ah[mf][0], ah[mf][1], ah[mf][2], ah[mf][3], sAh + aoff + mf * 16 * ROWB);
            uint32_t bh[4][2];
#pragma unroll
            for (int ng = 0; ng < 2; ng++)
                ldm_x4(bh[2 * ng][0], bh[2 * ng][1], bh[2 * ng + 1][0], bh[2 * ng + 1][1],
                       sBh + boff + ng * 16 * ROWB);

            if constexpr (TERMS == 3) {
                const uint32_t sAl = sAh + TILEB;
                const uint32_t sBl = sAh + 3 * TILEB;
                uint32_t bl[4][2];
#pragma unroll
                for (int ng = 0; ng < 2; ng++)
                    ldm_x4(bl[2 * ng][0], bl[2 * ng][1], bl[2 * ng + 1][0], bl[2 * ng + 1][1],
                           sBl + boff + ng * 16 * ROWB);
#pragma unroll
                for (int mf = 0; mf < 4; mf++)
#pragma unroll
                    for (int nf = 0; nf < 4; nf++) {
                        mma_t<ISBF16>(acc[mf][nf], ah[mf], bh[nf]);
                        mma_t<ISBF16>(acc[mf][nf], ah[mf], bl[nf]);
                    }
#pragma unroll
                for (int mf = 0; mf < 4; mf++)
                    ldm_x4(ah[mf][0], ah[mf][1], ah[mf][2], ah[mf][3], sAl + aoff + mf * 16 * ROWB);
#pragma unroll
                for (int mf = 0; mf < 4; mf++)
#pragma unroll
                    for (int nf = 0; nf < 4; nf++)
                        mma_t<ISBF16>(acc[mf][nf], ah[mf], bh[nf]);
            } else {
#pragma unroll
                for (int mf = 0; mf < 4; mf++)
#pragma unroll
                    for (int nf = 0; nf < 4; nf++)
                        mma_t<ISBF16>(acc[mf][nf], ah[mf], bh[nf]);
            }
        }
    }

    // epilogue
    const int rl = lane >> 2, cl = (lane & 3) * 2;
#pragma unroll
    for (int mf = 0; mf < 4; mf++) {
        const int row0 = bm + wm + mf * 16 + rl;
#pragma unroll
        for (int nf = 0; nf < 4; nf++) {
            const int col = bn + wn + nf * 8 + cl;
            const float b0 = bias[col], b1 = bias[col + 1];
            float v0 = acc[mf][nf][0] + b0, v1 = acc[mf][nf][1] + b1;
            float v2 = acc[mf][nf][2] + b0, v3 = acc[mf][nf][3] + b1;
            if (eop == 1) {
                const float* r0 = res + (size_t)row0 * N + col;
                const float* r1 = res + (size_t)(row0 + 8) * N + col;
                v0 += r0[0]; v1 += r0[1]; v2 += r1[0]; v3 += r1[1];
            } else if (eop == 2) {
                v0 = fmaxf(v0, 0.f); v1 = fmaxf(v1, 0.f);
                v2 = fmaxf(v2, 0.f); v3 = fmaxf(v3, 0.f);
                *(__half2*)(Chi + (size_t)row0 * N + col)       = __floats2half2_rn(v0, v1);
                *(__half2*)(Chi + (size_t)(row0 + 8) * N + col) = __floats2half2_rn(v2, v3);
                continue;
            }
            *(float2*)(C + (size_t)row0 * N + col) = make_float2(v0, v1);
            *(float2*)(C + (size_t)(row0 + 8) * N + col) = make_float2(v2, v3);
        }
    }

    // piggybacked constant fill of the score output (streaming stores)
    if (fillp) {
        const int nv4 = fillPerBlk >> 2;
        const int blin = blockIdx.y * gridDim.x + blockIdx.x;
        float4* dst = (float4*)fillp + (size_t)blin * nv4;
        const float c = 1.0f / Lz;
        const float4 f4 = make_float4(c, c, c, c);
        for (int i = tid; i < nv4; i += 256) __stcs(dst + i, f4);
    }
}

// ---------------- x -> bf16 hi/lo + fp16, one read ----------------
__global__ void __launch_bounds__(256)
split_x_kernel(const float* __restrict__ src, __nv_bfloat16* __restrict__ hi,
               __nv_bfloat16* __restrict__ lo, __half* __restrict__ f16)
{
    const size_t i = (size_t)blockIdx.x * 256 + threadIdx.x;
    const float4 v = ((const float4*)src)[i];
    __nv_bfloat16 h0 = __float2bfloat16(v.x), h1 = __float2bfloat16(v.y);
    __nv_bfloat16 h2 = __float2bfloat16(v.z), h3 = __float2bfloat16(v.w);
    __nv_bfloat162 ha; ha.x = h0; ha.y = h1;
    __nv_bfloat162 hb; hb.x = h2; hb.y = h3;
    ((__nv_bfloat162*)hi)[i * 2 + 0] = ha;
    ((__nv_bfloat162*)hi)[i * 2 + 1] = hb;
    __nv_bfloat162 la, lb;
    la.x = __float2bfloat16(v.x - __bfloat162float(h0));
    la.y = __float2bfloat16(v.y - __bfloat162float(h1));
    lb.x = __float2bfloat16(v.z - __bfloat162float(h2));
    lb.y = __float2bfloat16(v.w - __bfloat162float(h3));
    ((__nv_bfloat162*)lo)[i * 2 + 0] = la;
    ((__nv_bfloat162*)lo)[i * 2 + 1] = lb;
    ((__half2*)f16)[i * 2 + 0] = __floats2half2_rn(v.x, v.y);
    ((__half2*)f16)[i * 2 + 1] = __floats2half2_rn(v.z, v.w);
}

// ---------------- weight transpose + bf16 hi/lo split ----------------
__global__ void __launch_bounds__(256)
tsplit_kernel(const float* __restrict__ src, __nv_bfloat16* __restrict__ hi,
              __nv_bfloat16* __restrict__ lo, int K, int N)
{
    __shared__ float tile[32][33];
    const int tx = threadIdx.x & 31, ty = threadIdx.x >> 5;
    const int n0 = blockIdx.x * 32, k0 = blockIdx.y * 32;
#pragma unroll
    for (int i = 0; i < 4; i++)
        tile[ty + 8 * i][tx] = src[(size_t)(k0 + ty + 8 * i) * N + n0 + tx];
    __syncthreads();
#pragma unroll
    for (int i = 0; i < 4; i++) {
        const int n = n0 + ty + 8 * i, k = k0 + tx;
        const float v = tile[tx][ty + 8 * i];
        const __nv_bfloat16 h = __float2bfloat16(v);
        hi[(size_t)n * K + k] = h;
        lo[(size_t)n * K + k] = __float2bfloat16(v - __bfloat162float(h));
    }
}

// ---------------- weight transpose -> fp16 ----------------
__global__ void __launch_bounds__(256)
tsplitf_kernel(const float* __restrict__ src, __half* __restrict__ dst, int K, int N)
{
    __shared__ float tile[32][33];
    const int tx = threadIdx.x & 31, ty = threadIdx.x >> 5;
    const int n0 = blockIdx.x * 32, k0 = blockIdx.y * 32;
#pragma unroll
    for (int i = 0; i < 4; i++)
        tile[ty + 8 * i][tx] = src[(size_t)(k0 + ty + 8 * i) * N + n0 + tx];
    __syncthreads();
#pragma unroll
    for (int i = 0; i < 4; i++) {
        const int n = n0 + ty + 8 * i, k = k0 + tx;
        dst[(size_t)n * K + k] = __float2half(tile[tx][ty + 8 * i]);
    }
}

// ---------------- Sampled scores + fill chunk ----------------
__global__ void compute_m_kernel(const int* __restrict__ idx, float* __restrict__ fillp)
{
    // piggybacked fill: 2048 floats per block (512 float4)
    {
        const float c = 1.0f / Lz;
        const float4 f4 = make_float4(c, c, c, c);
        float4* dst = (float4*)fillp + (size_t)blockIdx.x * 512;
        __stcs(dst + threadIdx.x, f4);
        __stcs(dst + threadIdx.x + 256, f4);
    }

    const int gw = (blockIdx.x * blockDim.x + threadIdx.x) >> 5;
    const int lane = threadIdx.x & 31;
    const int l = gw & (Lz - 1);
    const int bh = gw >> 10;
    const int h = bh & (Hz - 1), b = bh >> 3;

    const float2* qrow = (const float2*)(g_Q + (size_t)(b * Lz + l) * DMz + h * DKz);
    const float2 q2 = qrow[lane];
    float mx = -INFINITY, sum = 0.f;
#pragma unroll 1
    for (int s = 0; s < Uz; s++) {
        const int j = idx[l * Uz + s];
        const float2 k2 = ((const float2*)(g_K + (size_t)(b * Lz + j) * DMz + h * DKz))[lane];
        float p = q2.x * k2.x + q2.y * k2.y;
#pragma unroll
        for (int o = 16; o; o >>= 1) p += __shfl_xor_sync(0xffffffffu, p, o);
        mx = fmaxf(mx, p);
        sum += p;
    }
    if (lane == 0) g_M[bh * Lz + l] = mx - sum * (1.0f / Uz);
}

// ---------------- top-35 per (b,h) ----------------
__global__ void __launch_bounds__(256) topk_kernel()
{
    const int bh = blockIdx.x;
    const int tid = threadIdx.x;
    const int wid = tid >> 5, lane = tid & 31;
    __shared__ float vals[Lz];
    __shared__ float wv[8];
    __shared__ int   wi[8];

    for (int l = tid; l < Lz; l += 256) {
        vals[l] = g_M[bh * Lz + l];
        g_rowmap[bh * Lz + l] = -1;
    }
    __syncthreads();

    for (int u = 0; u < Uz; u++) {
        float best = -INFINITY; int bi = 0x7fffffff;
#pragma unroll
        for (int c = 0; c < 4; c++) {
            const int l = tid + c * 256;
            const float v = vals[l];
            if (v > best) { best = v; bi = l; }
        }
#pragma unroll
        for (int o = 16; o; o >>= 1) {
            const float ov = __shfl_xor_sync(0xffffffffu, best, o);
            const int   oi = __shfl_xor_sync(0xffffffffu, bi, o);
            if (ov > best || (ov == best && oi < bi)) { best = ov; bi = oi; }
        }
        if (lane == 0) { wv[wid] = best; wi[wid] = bi; }
        __syncthreads();
        if (tid == 0) {
            float fb = wv[0]; int fi = wi[0];
#pragma unroll
            for (int w = 1; w < 8; w++) {
                if (wv[w] > fb || (wv[w] == fb && wi[w] < fi)) { fb = wv[w]; fi = wi[w]; }
            }
            g_Mtop[bh * Uz + u] = fi;
            g_rowmap[bh * Lz + fi] = u;
            vals[fi] = -INFINITY;
        }
        __syncthreads();
    }
}

// ---------------- scores = Q_top @ K^T / 8 ----------------
__global__ void __launch_bounds__(256) scores_kernel()
{
    const int bh = blockIdx.x;
    const int b = bh >> 3, h = bh & (Hz - 1);
    const int tid = threadIdx.x;
    __shared__ float Qr[Uz * DKz];

    for (int i = tid; i < Uz * DKz; i += 256) {
        const int u = i / DKz, d = i - u * DKz;
        const int l = g_Mtop[bh * Uz + u];
        Qr[i] = g_Q[(size_t)(b * Lz + l) * DMz + h * DKz + d];
    }
    __syncthreads();

    for (int l = tid; l < Lz; l += 256) {
        float acc[Uz];
#pragma unroll
        for (int u = 0; u < Uz; u++) acc[u] = 0.f;
        const float* krow = g_K + (size_t)(b * Lz + l) * DMz + h * DKz;
#pragma unroll 4
        for (int d = 0; d < DKz; d++) {
            const float kd = krow[d];
#pragma unroll
            for (int u = 0; u < Uz; u++) acc[u] += kd * Qr[u * DKz + d];
        }
#pragma unroll
        for (int u = 0; u < Uz; u++)
            g_attn[((size_t)bh * Uz + u) * Lz + l] = acc[u] * 0.125f;
    }
}

// ---------------- row softmax over L ----------------
__global__ void __launch_bounds__(256) softmax_kernel()
{
    const int row = blockIdx.x;
    float* p = g_attn + (size_t)row * Lz;
    const int tid = threadIdx.x;
    __shared__ float red[256];

    float4 v = ((float4*)p)[tid];
    float m = fmaxf(fmaxf(v.x, v.y), fmaxf(v.z, v.w));
    red[tid] = m; __syncthreads();
    for (int s = 128; s; s >>= 1) { if (tid < s) red[tid] = fmaxf(red[tid], red[tid + s]); __syncthreads(); }
    m = red[0]; __syncthreads();

    v.x = __expf(v.x - m); v.y = __expf(v.y - m);
    v.z = __expf(v.z - m); v.w = __expf(v.w - m);
    red[tid] = v.x + v.y + v.z + v.w; __syncthreads();
    for (int s = 128; s; s >>= 1) { if (tid < s) red[tid] += red[tid + s]; __syncthreads(); }
    const float inv = 1.0f / red[0];
    v.x *= inv; v.y *= inv; v.z *= inv; v.w *= inv;
    ((float4*)p)[tid] = v;
}

// ---------------- context (+fused V-mean): block per (b,h), V streamed once ----------------
__global__ void __launch_bounds__(256) context_kernel()
{
    const int bh = blockIdx.x;
    const int b = bh >> 3, h = bh & (Hz - 1);
    const int t = threadIdx.x;
    const int d = t & 63, ug = t >> 6;
    __shared__ float sat[Uz][129];

    float acc[9];
#pragma unroll
    for (int k = 0; k < 9; k++) acc[k] = 0.f;
    float vsum = 0.f;

    for (int c = 0; c < 8; c++) {
        for (int i = t; i < Uz * 128; i += 256) {
            const int u = i >> 7, li = i & 127;
            sat[u][li] = g_attn[((size_t)bh * Uz + u) * Lz + c * 128 + li];
        }
        __syncthreads();
        const float* vb = g_V + (size_t)(b * Lz + c * 128) * DMz + h * DVz + d;
#pragma unroll 4
        for (int i = 0; i < 128; i++) {
            const float v = vb[(size_t)i * DMz];
            vsum += v;
#pragma unroll
            for (int k = 0; k < 9; k++) {
                const int u = ug + 4 * k;
                if (u < Uz) acc[k] += sat[u][i] * v;
            }
        }
        __syncthreads();
    }
#pragma unroll
    for (int k = 0; k < 9; k++) {
        const int u = ug + 4 * k;
        if (u < Uz) g_ctxrow[(bh * Uz + u) * DVz + d] = acc[k];
    }
    if (ug == 0) g_vmean[bh * DVz + d] = vsum * (1.0f / Lz);
}

// ---------------- copy selected attn rows into pre-filled score output ----------------
__global__ void __launch_bounds__(256) copy_scores_kernel(float* __restrict__ outp)
{
    const int bhu = blockIdx.x;            // bh*Uz + u
    const int bh = bhu / Uz;
    const int l = g_Mtop[bhu];
    const float4* src = (const float4*)(g_attn + (size_t)bhu * Lz);
    float4* dst = (float4*)(outp + ((size_t)bh * Lz + l) * Lz);
    dst[threadIdx.x] = src[threadIdx.x];
}

// ---------------- assemble ctx -> fp16 ----------------
__global__ void __launch_bounds__(256) ctx_assemble_kernel(__half* __restrict__ dst)
{
    const size_t gidx = (size_t)blockIdx.x * 256 + threadIdx.x;
    const int row = (int)(gidx >> 9);
    const int c = (int)(gidx & 511);
    const int h = c >> 6, d = c & 63;
    const int b = row >> 10, l = row & (Lz - 1);
    const int bh = b * Hz + h;
    const int u = g_rowmap[bh * Lz + l];
    const float v = (u < 0) ? g_vmean[bh * DVz + d]
                            : g_ctxrow[(bh * Uz + u) * DVz + d];
    dst[gidx] = __float2half(v);
}

// ---------------- LayerNorm (512), optional fused fp16 output ----------------
__global__ void __launch_bounds__(256)
ln_kernel(const float* __restrict__ in, const float* __restrict__ g,
          const float* __restrict__ beta, float* __restrict__ out,
          __half* __restrict__ outf)
{
    const int row = blockIdx.x;
    const int tid = threadIdx.x;
    __shared__ float red[256];
    const float* r = in + (size_t)row * DMz;
    const float a = r[tid], b2 = r[tid + 256];

    red[tid] = a + b2; __syncthreads();
    for (int s = 128; s; s >>= 1) { if (tid < s) red[tid] += red[tid + s]; __syncthreads(); }
    const float mean = red[0] * (1.0f / DMz);
    __syncthreads();
    const float d0 = a - mean, d1 = b2 - mean;
    red[tid] = d0 * d0 + d1 * d1; __syncthreads();
    for (int s = 128; s; s >>= 1) { if (tid < s) red[tid] += red[tid + s]; __syncthreads(); }
    const float inv = rsqrtf(red[0] * (1.0f / DMz) + EPSz);
    const float o0 = g[tid]       * d0 * inv + beta[tid];
    const float o1 = g[tid + 256] * d1 * inv + beta[tid + 256];
    out[(size_t)row * DMz + tid]       = o0;
    out[(size_t)row * DMz + tid + 256] = o1;
    if (outf) {
        outf[(size_t)row * DMz + tid]       = __float2half(o0);
        outf[(size_t)row * DMz + tid + 256] = __float2half(o1);
    }
}

// ---------------- launch ----------------
extern "C" void kernel_launch(void* const* d_in, const int* in_sizes, int n_in,
                              void* d_out, int out_size)
{
    const float* x   = (const float*)d_in[0];
    const float* Wq  = (const float*)d_in[1];
    const float* bq  = (const float*)d_in[2];
    const float* Wk  = (const float*)d_in[3];
    const float* bk  = (const float*)d_in[4];
    const float* Wv  = (const float*)d_in[5];
    const float* bv  = (const float*)d_in[6];
    const float* Wo  = (const float*)d_in[7];
    const float* bo  = (const float*)d_in[8];
    const float* g1  = (const float*)d_in[9];
    const float* be1 = (const float*)d_in[10];
    const float* W1  = (const float*)d_in[11];
    const float* bf1 = (const float*)d_in[12];
    const float* W2  = (const float*)d_in[13];
    const float* bf2 = (const float*)d_in[14];
    const float* g2  = (const float*)d_in[15];
    const float* be2 = (const float*)d_in[16];
    const int*   idx = (const int*)d_in[17];
    float* out = (float*)d_out;
    float* score = out + (size_t)ROWSz * DMz;   // BHz*Lz*Lz floats

    float *Qp, *Kp, *Vp, *yp, *x1p, *y2p;
    cudaGetSymbolAddress((void**)&Qp,   g_Q);
    cudaGetSymbolAddress((void**)&Kp,   g_K);
    cudaGetSymbolAddress((void**)&Vp,   g_V);
    cudaGetSymbolAddress((void**)&yp,   g_y);
    cudaGetSymbolAddress((void**)&x1p,  g_x1);
    cudaGetSymbolAddress((void**)&y2p,  g_y2);

    __nv_bfloat16 *xh, *xl, *WqTh, *WqTl, *WkTh, *WkTl;
    __half *xf, *cf, *x1f, *hf, *WvTf, *WoTf, *W1Tf, *W2Tf;
    cudaGetSymbolAddress((void**)&xh, g_xh);     cudaGetSymbolAddress((void**)&xl, g_xl);
    cudaGetSymbolAddress((void**)&WqTh, g_WqTh); cudaGetSymbolAddress((void**)&WqTl, g_WqTl);
    cudaGetSymbolAddress((void**)&WkTh, g_WkTh); cudaGetSymbolAddress((void**)&WkTl, g_WkTl);
    cudaGetSymbolAddress((void**)&xf, g_xf);     cudaGetSymbolAddress((void**)&cf, g_cf);
    cudaGetSymbolAddress((void**)&x1f, g_x1f);   cudaGetSymbolAddress((void**)&hf, g_hf);
    cudaGetSymbolAddress((void**)&WvTf, g_WvTf); cudaGetSymbolAddress((void**)&WoTf, g_WoTf);
    cudaGetSymbolAddress((void**)&W1Tf, g_W1Tf); cudaGetSymbolAddress((void**)&W2Tf, g_W2Tf);

    const int SM3 = 2 * 4 * TILEB;   // 81920
    const int SM1 = 2 * 2 * TILEB;   // 40960
    cudaFuncSetAttribute(gemm_kernel<3, true>,
                         cudaFuncAttributeMaxDynamicSharedMemorySize, SM3);
    cudaFuncSetAttribute(gemm_kernel<1, false>,
                         cudaFuncAttributeMaxDynamicSharedMemorySize, SM1);

    const dim3 gN512(4, 128);
    const dim3 gN2048(16, 128);

    // fill partition: 3 GEMM launches x 512 blocks x 65536 floats = 100663296,
    // compute_m 16384 blocks x 2048 floats = 33554432  -> total 134217728 = BHz*Lz*Lz
    const int FPB_GEMM = 65536;
    float* fill0 = score;
    float* fill1 = score + (size_t)512 * FPB_GEMM;
    float* fill2 = score + (size_t)1024 * FPB_GEMM;
    float* fill3 = score + (size_t)1536 * FPB_GEMM;

    // conversions for QKV (launch #6 = GEMM Q for ncu)
    split_x_kernel<<<(ROWSz * DMz) / 1024, 256>>>(x, xh, xl, xf);          // 1
    tsplit_kernel<<<dim3(16, 16), 256>>>(Wq, WqTh, WqTl, DMz, DMz);        // 2
    tsplit_kernel<<<dim3(16, 16), 256>>>(Wk, WkTh, WkTl, DMz, DMz);        // 3
    tsplitf_kernel<<<dim3(16, 16), 256>>>(Wv, WvTf, DMz, DMz);             // 4
    tsplitf_kernel<<<dim3(16, 16), 256>>>(Wo, WoTf, DMz, DMz);             // 5

    // QKV projections (+score fill)
    gemm_kernel<3, true><<<gN512, 256, SM3>>>((const uint16_t*)xh, (const uint16_t*)xl,
        (const uint16_t*)WqTh, (const uint16_t*)WqTl, bq, nullptr, Qp, nullptr,
        fill0, FPB_GEMM, ROWSz, DMz, DMz, 0);                              // 6 (ncu)
    gemm_kernel<3, true><<<gN512, 256, SM3>>>((const uint16_t*)xh, (const uint16_t*)xl,
        (const uint16_t*)WkTh, (const uint16_t*)WkTl, bk, nullptr, Kp, nullptr,
        fill1, FPB_GEMM, ROWSz, DMz, DMz, 0);                              // 7
    gemm_kernel<1, false><<<gN512, 256, SM1>>>((const uint16_t*)xf, nullptr,
        (const uint16_t*)WvTf, nullptr, bv, nullptr, Vp, nullptr,
        fill2, FPB_GEMM, ROWSz, DMz, DMz, 0);                              // 8

    // remaining weight conversions
    tsplitf_kernel<<<dim3(64, 16), 256>>>(W1, W1Tf, DMz, DHz);
    tsplitf_kernel<<<dim3(16, 64), 256>>>(W2, W2Tf, DHz, DMz);

    // ProbSparse attention
    compute_m_kernel<<<(BHz * Lz) / 8, 256>>>(idx, fill3);
    topk_kernel<<<BHz, 256>>>();
    scores_kernel<<<BHz, 256>>>();
    softmax_kernel<<<BHz * Uz, 256>>>();
    context_kernel<<<BHz, 256>>>();
    copy_scores_kernel<<<BHz * Uz, 256>>>(score);
    ctx_assemble_kernel<<<(ROWSz * DMz) / 256, 256>>>(cf);

    // Wo projection + residual, LN1 (fused fp16 x1)
    gemm_kernel<1, false><<<gN512, 256, SM1>>>((const uint16_t*)cf, nullptr,
        (const uint16_t*)WoTf, nullptr, bo, x, yp, nullptr,
        nullptr, 0, ROWSz, DMz, DMz, 1);
    ln_kernel<<<ROWSz, 256>>>(yp, g1, be1, x1p, x1f);

    // FFN
    gemm_kernel<1, false><<<gN2048, 256, SM1>>>((const uint16_t*)x1f, nullptr,
        (const uint16_t*)W1Tf, nullptr, bf1, nullptr, nullptr, (uint16_t*)hf,
        nullptr, 0, ROWSz, DHz, DMz, 2);
    gemm_kernel<1, false><<<gN512, 256, SM1>>>((const uint16_t*)hf, nullptr,
        (const uint16_t*)W2Tf, nullptr, bf2, x1p, y2p, nullptr,
        nullptr, 0, ROWSz, DMz, DHz, 1);
    ln_kernel<<<ROWSz, 256>>>(y2p, g2, be2, out, nullptr);
}